// round 7
// baseline (speedup 1.0000x reference)
#include <cuda_runtime.h>
#include <math.h>

#define NN 8192
#define TT 32
#define FF 16
#define HH 128
#define NHEADS 4
#define EE 2048
#define NZ 65536
#define NH (NN*HH)

// ----------------- static device scratch (no allocs) -----------------
__device__ float g_scale1[512], g_shift1[512], g_sum1[512], g_sq1[512];
__device__ float g_scale2[HH], g_shift2[HH], g_sum2[HH], g_sq2[HH];
__device__ float g_WhhT[384 * HH];
__device__ float g_h0[NH], g_h1[NH];
__device__ float g_ctx[NN * TT * HH];
__device__ float g_q[NH];
__device__ float g_comb[NN * 2 * HH];
__device__ float g_xbn[NH];
__device__ float g_ef[EE * HH];
__device__ float g_xw[NN * 512];
__device__ float g_ew[EE * 512];
__device__ float g_xa[NN * NHEADS];
__device__ float g_ea[EE * NHEADS];
__device__ float g_alpha[NZ * NHEADS];
__device__ unsigned g_segmax[NN * NHEADS];
__device__ float g_segsum[NN * NHEADS];
__device__ float g_Dinv[NN];
__device__ float g_eout[EE * NHEADS * HH];
__device__ float g_x1[NH];
__device__ int g_cnt[NN], g_cursor[NN], g_rowptr[NN + 1], g_adj[NZ];

// ----------------- helpers -----------------
__device__ __forceinline__ unsigned fenc(float a) {
    unsigned u = __float_as_uint(a);
    return (u & 0x80000000u) ? ~u : (u | 0x80000000u);
}
__device__ __forceinline__ float fdec(unsigned u) {
    return (u & 0x80000000u) ? __uint_as_float(u & 0x7FFFFFFFu) : __uint_as_float(~u);
}
__device__ __forceinline__ float sigmf(float x) { return 1.f / (1.f + expf(-x)); }

__global__ void zero_k(float* p, int n) {
    for (int i = blockIdx.x * blockDim.x + threadIdx.x; i < n; i += gridDim.x * blockDim.x)
        p[i] = 0.f;
}

// ----------------- batchnorm -----------------
__global__ void bn_partial(const float* __restrict__ x, float* sum, float* sq, int ncols) {
    int col = blockIdx.x * blockDim.x + threadIdx.x;
    if (col >= ncols) return;
    int chunk = NN / gridDim.y, r0 = blockIdx.y * chunk;
    float s = 0.f, ss = 0.f;
    for (int r = r0; r < r0 + chunk; r++) {
        float v = x[(size_t)r * ncols + col];
        s += v; ss += v * v;
    }
    atomicAdd(&sum[col], s);
    atomicAdd(&sq[col], ss);
}
__global__ void bn_finalize(const float* sum, const float* sq, const float* g,
                            const float* b, float* scale, float* shift, int ncols) {
    int c = blockIdx.x * blockDim.x + threadIdx.x;
    if (c >= ncols) return;
    float m = sum[c] * (1.f / NN);
    float v = sq[c] * (1.f / NN) - m * m;
    float sc = rsqrtf(v + 1e-5f) * g[c];
    scale[c] = sc; shift[c] = b[c] - m * sc;
}
__global__ void bn_apply(const float* __restrict__ x, const float* scale,
                         const float* shift, float* y) {
    int i = blockIdx.x * blockDim.x + threadIdx.x;
    if (i >= NH) return;
    int c = i & (HH - 1);
    y[i] = x[i] * scale[c] + shift[c];
}

// ----------------- GRU -----------------
__global__ void transpose_whh(const float* __restrict__ Whh, float* WhhT) {
    int idx = blockIdx.x * blockDim.x + threadIdx.x;
    if (idx >= 384 * 128) return;
    int r = idx >> 7, k = idx & 127;
    WhhT[k * 384 + r] = Whh[idx];
}

// grid (NN/64, 4), block 256: 64 nodes x 32 hidden cols per block
__global__ void gru_step(const float* __restrict__ price,
                         const float* __restrict__ Wih, const float* __restrict__ bih,
                         const float* __restrict__ bhh,
                         const float* __restrict__ h_in, float* __restrict__ h_out, int t) {
    __shared__ float sh[128 * 65];
    __shared__ float sx[64 * 17];
    __shared__ float sWih[16 * 96];
    __shared__ float sbih[96], sbhh[96];
    int tid = threadIdx.x, node0 = blockIdx.x * 64, jtile = blockIdx.y * 32;

    for (int idx = tid; idx < 64 * 128; idx += 256) {
        int nd = idx >> 7, k = idx & 127;
        sh[k * 65 + nd] = h_in[(node0 + nd) * HH + k];
    }
    for (int idx = tid; idx < 64 * 16; idx += 256) {
        int nd = idx >> 4, f = idx & 15, col = t * 16 + f;
        sx[nd * 17 + f] = price[(size_t)(node0 + nd) * 512 + col] * g_scale1[col] + g_shift1[col];
    }
    for (int idx = tid; idx < 96 * 16; idx += 256) {
        int row = idx >> 4, f = idx & 15, g = row >> 5, jj = row & 31;
        sWih[f * 96 + row] = Wih[(g * 128 + jtile + jj) * 16 + f];
    }
    if (tid < 96) {
        int g = tid >> 5, jj = tid & 31;
        sbih[tid] = bih[g * 128 + jtile + jj];
        sbhh[tid] = bhh[g * 128 + jtile + jj];
    }
    __syncthreads();

    int jj = tid & 31, nbase = (tid >> 5) * 8;
    float aR[8], aZ[8], aNx[8], aNh[8];
    float br = sbih[jj] + sbhh[jj], bz = sbih[32 + jj] + sbhh[32 + jj];
    float bnx = sbih[64 + jj], bnh = sbhh[64 + jj];
#pragma unroll
    for (int i = 0; i < 8; i++) { aR[i] = br; aZ[i] = bz; aNx[i] = bnx; aNh[i] = bnh; }

    const float* wp = g_WhhT + jtile + jj;
#pragma unroll 2
    for (int k = 0; k < 128; k++) {
        float w0 = __ldg(wp + k * 384);
        float w1 = __ldg(wp + k * 384 + 128);
        float w2 = __ldg(wp + k * 384 + 256);
#pragma unroll
        for (int i = 0; i < 8; i++) {
            float hv = sh[k * 65 + nbase + i];
            aR[i] += hv * w0; aZ[i] += hv * w1; aNh[i] += hv * w2;
        }
    }
#pragma unroll
    for (int f = 0; f < 16; f++) {
        float u0 = sWih[f * 96 + jj], u1 = sWih[f * 96 + 32 + jj], u2 = sWih[f * 96 + 64 + jj];
#pragma unroll
        for (int i = 0; i < 8; i++) {
            float xv = sx[(nbase + i) * 17 + f];
            aR[i] += xv * u0; aZ[i] += xv * u1; aNx[i] += xv * u2;
        }
    }
    int j = jtile + jj;
#pragma unroll
    for (int i = 0; i < 8; i++) {
        int nd = nbase + i;
        float r = sigmf(aR[i]), z = sigmf(aZ[i]);
        float nv = tanhf(aNx[i] + r * aNh[i]);
        float hnew = (1.f - z) * nv + z * sh[j * 65 + nd];
        int gn = node0 + nd;
        h_out[gn * HH + j] = hnew;
        g_ctx[(size_t)gn * (TT * HH) + t * HH + j] = hnew;
    }
}

// ----------------- generic NT sgemm: C = act(A(M,K) @ B(Nc,K)^T) -----------------
__global__ void gemm_nt(const float* __restrict__ A, const float* __restrict__ B,
                        float* __restrict__ C, int M, int Nc, int K, int act) {
    __shared__ float As[16 * 68], Bs[16 * 68];
    int tid = threadIdx.x, n0 = blockIdx.x * 64, m0 = blockIdx.y * 64;
    int lrow = tid >> 2, kq = tid & 3, tx = tid & 15, ty = tid >> 4;
    float c[4][4];
#pragma unroll
    for (int i = 0; i < 4; i++)
#pragma unroll
        for (int jv = 0; jv < 4; jv++) c[i][jv] = 0.f;

    for (int k0 = 0; k0 < K; k0 += 16) {
        float4 av = *(const float4*)&A[(size_t)(m0 + lrow) * K + k0 + kq * 4];
        float4 bv = *(const float4*)&B[(size_t)(n0 + lrow) * K + k0 + kq * 4];
        __syncthreads();
        As[(kq * 4 + 0) * 68 + lrow] = av.x; As[(kq * 4 + 1) * 68 + lrow] = av.y;
        As[(kq * 4 + 2) * 68 + lrow] = av.z; As[(kq * 4 + 3) * 68 + lrow] = av.w;
        Bs[(kq * 4 + 0) * 68 + lrow] = bv.x; Bs[(kq * 4 + 1) * 68 + lrow] = bv.y;
        Bs[(kq * 4 + 2) * 68 + lrow] = bv.z; Bs[(kq * 4 + 3) * 68 + lrow] = bv.w;
        __syncthreads();
#pragma unroll
        for (int kk = 0; kk < 16; kk++) {
            float4 a = *(const float4*)&As[kk * 68 + ty * 4];
            float4 b = *(const float4*)&Bs[kk * 68 + tx * 4];
            float ar[4] = {a.x, a.y, a.z, a.w}, br[4] = {b.x, b.y, b.z, b.w};
#pragma unroll
            for (int i = 0; i < 4; i++)
#pragma unroll
                for (int jv = 0; jv < 4; jv++) c[i][jv] += ar[i] * br[jv];
        }
    }
#pragma unroll
    for (int i = 0; i < 4; i++)
#pragma unroll
        for (int jv = 0; jv < 4; jv++) {
            float v = c[i][jv];
            if (act == 1) v = tanhf(v);
            C[(size_t)(m0 + ty * 4 + i) * Nc + n0 + tx * 4 + jv] = v;
        }
}

// ----------------- temporal attention middle -----------------
__global__ void attn_mid(const float* __restrict__ ae, const float* __restrict__ ab) {
    __shared__ float sctx[32 * 129], sq[128], sw[32], sbt[32];
    int n = blockIdx.x, tid = threadIdx.x;
    sq[tid] = g_q[n * HH + tid];
    for (int idx = tid; idx < TT * HH; idx += 128) {
        int t = idx >> 7, k = idx & 127;
        sctx[t * 129 + k] = g_ctx[(size_t)n * (TT * HH) + idx];
    }
    __syncthreads();
    if (tid < 32) {
        float s = 0.f;
        for (int k = 0; k < 128; k++) s += sq[k] * sctx[tid * 129 + k];
        float m = s;
#pragma unroll
        for (int o = 16; o; o >>= 1) m = fmaxf(m, __shfl_xor_sync(0xffffffffu, m, o));
        float e = expf(s - m), su = e;
#pragma unroll
        for (int o = 16; o; o >>= 1) su += __shfl_xor_sync(0xffffffffu, su, o);
        sw[tid] = e / su;
        sbt[tid] = expf(-ab[n] * (float)(31 - tid));
    }
    __syncthreads();
    float aen = ae[n], acc = 0.f;
#pragma unroll 4
    for (int t = 0; t < TT; t++) {
        float mx = sw[t] * sctx[t * 129 + tid];
        acc += mx + fmaxf(aen * mx * sbt[t], 0.f);
    }
    g_comb[n * 256 + tid] = acc;
    g_comb[n * 256 + 128 + tid] = sq[tid];
}

// ----------------- CSR build (by src) -----------------
__global__ void count_src(const int* __restrict__ e0, int* cnt) {
    int i = blockIdx.x * blockDim.x + threadIdx.x;
    if (i < NZ) atomicAdd(&cnt[e0[i]], 1);
}
__global__ void scan_csr(const int* __restrict__ cnt, int* rowptr, float* Dinv) {
    __shared__ int s[1024];
    int tid = threadIdx.x, base = tid * 8, loc[8], sum = 0;
#pragma unroll
    for (int j = 0; j < 8; j++) { loc[j] = sum; sum += cnt[base + j]; }
    s[tid] = sum;
    __syncthreads();
    for (int off = 1; off < 1024; off <<= 1) {
        int v = (tid >= off) ? s[tid - off] : 0;
        __syncthreads();
        s[tid] += v;
        __syncthreads();
    }
    int excl = tid ? s[tid - 1] : 0;
#pragma unroll
    for (int j = 0; j < 8; j++) {
        rowptr[base + j] = excl + loc[j];
        int c = cnt[base + j];
        Dinv[base + j] = c ? 1.f / (float)c : 0.f;
    }
    if (tid == 1023) rowptr[NN] = s[1023];
}
__global__ void fill_csr(const int* __restrict__ e0, const int* __restrict__ rowptr,
                         int* cursor, int* adj) {
    int i = blockIdx.x * blockDim.x + threadIdx.x;
    if (i >= NZ) return;
    int sg = e0[i];
    int p = atomicAdd(&cursor[sg], 1);
    adj[rowptr[sg] + p] = i;
}

// ----------------- hypergraph pieces -----------------
// edge feats: ef[d] = sum_j x[e0[d+j*E]]   (uses dst[i] = i % E structure)
__global__ void efeat(const int* __restrict__ e0, const float* __restrict__ x, float* ef) {
    int d = blockIdx.x, c = threadIdx.x;
    float a = 0.f;
#pragma unroll 4
    for (int j = 0; j < 32; j++) a += x[e0[d + j * EE] * HH + c];
    ef[d * HH + c] = a;
}

// out[r,h] = dot(xw[r,h,:], att[h*stride : +128])
__global__ void rowdot(const float* __restrict__ xw, const float* __restrict__ att,
                       int stride, int heads, float* __restrict__ out) {
    int r = blockIdx.x, h = threadIdx.x >> 5, lane = threadIdx.x & 31;
    const float* row = xw + (size_t)(r * heads + h) * HH;
    float s = 0.f;
#pragma unroll
    for (int m = 0; m < 4; m++) s += row[lane + 32 * m] * att[h * stride + lane + 32 * m];
#pragma unroll
    for (int o = 16; o; o >>= 1) s += __shfl_xor_sync(0xffffffffu, s, o);
    if (!lane) out[r * heads + h] = s;
}

__global__ void alpha_max(const int* __restrict__ e0, const int* __restrict__ e1,
                          const float* __restrict__ xa, const float* __restrict__ ea,
                          int heads) {
    int g = blockIdx.x * blockDim.x + threadIdx.x;
    if (g >= NZ * heads) return;
    int i = g / heads, h = g - i * heads;
    float a = xa[e0[i] * heads + h] + ea[e1[i] * heads + h];
    a = (a > 0.f) ? a : 0.2f * a;
    g_alpha[g] = a;
    atomicMax(&g_segmax[e0[i] * heads + h], fenc(a));
}
__global__ void alpha_exp(const int* __restrict__ e0, int heads) {
    int g = blockIdx.x * blockDim.x + threadIdx.x;
    if (g >= NZ * heads) return;
    int i = g / heads, h = g - i * heads;
    float ex = expf(g_alpha[g] - fdec(g_segmax[e0[i] * heads + h]));
    g_alpha[g] = ex;
    atomicAdd(&g_segsum[e0[i] * heads + h], ex);
}
__global__ void alpha_norm(const int* __restrict__ e0, int heads) {
    int g = blockIdx.x * blockDim.x + threadIdx.x;
    if (g >= NZ * heads) return;
    int i = g / heads, h = g - i * heads;
    g_alpha[g] /= (g_segsum[e0[i] * heads + h] + 1e-16f);
}

// eout[d,h,:] = (1/32) * sum_j alpha[d+jE,h] * xw[e0[d+jE],h,:]
template <int HT>
__global__ void eout_gather(const int* __restrict__ e0, const float* __restrict__ xw) {
    int d = blockIdx.x, c = threadIdx.x;
    float acc[HT];
#pragma unroll
    for (int h = 0; h < HT; h++) acc[h] = 0.f;
    for (int j = 0; j < 32; j++) {
        int i = d + j * EE, s = e0[i];
#pragma unroll
        for (int h = 0; h < HT; h++)
            acc[h] += g_alpha[i * HT + h] * xw[(size_t)(s * HT + h) * HH + c];
    }
#pragma unroll
    for (int h = 0; h < HT; h++)
        g_eout[(size_t)(d * HT + h) * HH + c] = acc[h] * (1.f / 32.f);
}

// node: out[s,c] = leaky0.2( Dinv[s]/HT * sum_h sum_{i in adj[s]} alpha[i,h]*eout[dst[i],h,c] + bias[c] )
template <int HT>
__global__ void node_out(const int* __restrict__ e1, const float* __restrict__ bias,
                         float* __restrict__ out) {
    int s = blockIdx.x, c = threadIdx.x;
    int b = g_rowptr[s], e = g_rowptr[s + 1];
    float a[HT];
#pragma unroll
    for (int h = 0; h < HT; h++) a[h] = 0.f;
    for (int k = b; k < e; k++) {
        int i = g_adj[k], d = e1[i];
#pragma unroll
        for (int h = 0; h < HT; h++)
            a[h] += g_alpha[i * HT + h] * g_eout[(size_t)(d * HT + h) * HH + c];
    }
    float v = 0.f;
#pragma unroll
    for (int h = 0; h < HT; h++) v += a[h];
    v = v * g_Dinv[s] * (1.f / HT) + bias[c];
    out[s * HH + c] = (v > 0.f) ? v : 0.2f * v;
}

// final head: out[n] = leaky0.01( dot(x2[n], Wo) + bo )
__global__ void head_k(const float* __restrict__ x2, const float* __restrict__ Wo,
                       const float* __restrict__ bo, float* __restrict__ out) {
    int n = blockIdx.x * 4 + (threadIdx.x >> 5), lane = threadIdx.x & 31;
    float s = 0.f;
#pragma unroll
    for (int m = 0; m < 4; m++) s += x2[n * HH + lane + 32 * m] * Wo[lane + 32 * m];
#pragma unroll
    for (int o = 16; o; o >>= 1) s += __shfl_xor_sync(0xffffffffu, s, o);
    if (!lane) {
        float v = s + bo[0];
        out[n] = (v > 0.f) ? v : 0.01f * v;
    }
}

// ----------------- host -----------------
static void* sym(const void* s) { void* p = 0; cudaGetSymbolAddress(&p, s); return p; }

extern "C" void kernel_launch(void* const* d_in, const int* in_sizes, int n_in,
                              void* d_out, int out_size) {
    const float* price = (const float*)d_in[0];
    const int*   e     = (const int*)d_in[1];
    const float* bn1g  = (const float*)d_in[2];
    const float* bn1b  = (const float*)d_in[3];
    const float* Wih   = (const float*)d_in[4];
    const float* Whh   = (const float*)d_in[5];
    const float* bih   = (const float*)d_in[6];
    const float* bhh   = (const float*)d_in[7];
    const float* Wq    = (const float*)d_in[8];
    const float* Wout  = (const float*)d_in[9];
    const float* ae    = (const float*)d_in[10];
    const float* ab    = (const float*)d_in[11];
    const float* bn2g  = (const float*)d_in[12];
    const float* bn2b  = (const float*)d_in[13];
    const float* W1    = (const float*)d_in[14];
    const float* att1  = (const float*)d_in[15];
    const float* bias1 = (const float*)d_in[16];
    const float* W2    = (const float*)d_in[17];
    const float* att2  = (const float*)d_in[18];
    const float* bias2 = (const float*)d_in[19];
    const float* Wo    = (const float*)d_in[20];
    const float* bo    = (const float*)d_in[21];
    const int* e0 = e;
    const int* e1 = e + NZ;

    float* out_nf = (float*)d_out;          // (N,H)
    float* out_x  = out_nf + NH;            // (N,H)
    float* out_o  = out_x + NH;             // (N,)

    float* p_sum1 = (float*)sym(g_sum1);  float* p_sq1 = (float*)sym(g_sq1);
    float* p_sum2 = (float*)sym(g_sum2);  float* p_sq2 = (float*)sym(g_sq2);
    float* p_sc1 = (float*)sym(g_scale1); float* p_sh1 = (float*)sym(g_shift1);
    float* p_sc2 = (float*)sym(g_scale2); float* p_sh2 = (float*)sym(g_shift2);
    float* p_h0 = (float*)sym(g_h0);      float* p_h1 = (float*)sym(g_h1);
    float* p_q = (float*)sym(g_q);        float* p_comb = (float*)sym(g_comb);
    float* p_xbn = (float*)sym(g_xbn);    float* p_ef = (float*)sym(g_ef);
    float* p_xw = (float*)sym(g_xw);      float* p_ew = (float*)sym(g_ew);
    float* p_xa = (float*)sym(g_xa);      float* p_ea = (float*)sym(g_ea);
    float* p_smax = (float*)sym(g_segmax); float* p_ssum = (float*)sym(g_segsum);
    float* p_x1 = (float*)sym(g_x1);      float* p_whhT = (float*)sym(g_WhhT);
    int* p_cnt = (int*)sym(g_cnt);        int* p_cur = (int*)sym(g_cursor);
    int* p_rp = (int*)sym(g_rowptr);      int* p_adj = (int*)sym(g_adj);
    float* p_Dinv = (float*)sym(g_Dinv);

    // BN1 stats
    zero_k<<<4, 256>>>(p_sum1, 512);
    zero_k<<<4, 256>>>(p_sq1, 512);
    bn_partial<<<dim3(4, 64), 128>>>(price, p_sum1, p_sq1, 512);
    bn_finalize<<<4, 128>>>(p_sum1, p_sq1, bn1g, bn1b, p_sc1, p_sh1, 512);

    // GRU
    zero_k<<<2048, 256>>>(p_h0, NH);
    transpose_whh<<<192, 256>>>(Whh, p_whhT);
    for (int t = 0; t < TT; t++) {
        float* hi = (t & 1) ? p_h1 : p_h0;
        float* ho = (t & 1) ? p_h0 : p_h1;
        gru_step<<<dim3(NN / 64, 4), 256>>>(price, Wih, bih, bhh, hi, ho, t);
    }
    // hT is in g_h0 (32 steps)

    // attention
    gemm_nt<<<dim3(2, NN / 64), 256>>>(p_h0, Wq, p_q, NN, 128, 128, 0);
    attn_mid<<<NN, 128>>>(ae, ab);
    gemm_nt<<<dim3(2, NN / 64), 256>>>(p_comb, Wout, out_nf, NN, 128, 256, 1);  // nf

    // BN2
    zero_k<<<1, 128>>>(p_sum2, HH);
    zero_k<<<1, 128>>>(p_sq2, HH);
    bn_partial<<<dim3(1, 64), 128>>>(out_nf, p_sum2, p_sq2, HH);
    bn_finalize<<<1, 128>>>(p_sum2, p_sq2, bn2g, bn2b, p_sc2, p_sh2, HH);
    bn_apply<<<NH / 256, 256>>>(out_nf, p_sc2, p_sh2, p_xbn);

    // CSR by src
    zero_k<<<16, 256>>>((float*)p_cnt, NN);
    count_src<<<NZ / 256, 256>>>(e0, p_cnt);
    scan_csr<<<1, 1024>>>(p_cnt, p_rp, p_Dinv);
    zero_k<<<16, 256>>>((float*)p_cur, NN);
    fill_csr<<<NZ / 256, 256>>>(e0, p_rp, p_cur, p_adj);

    // ---- conv 1 (4 heads) ----
    efeat<<<EE, 128>>>(e0, p_xbn, p_ef);
    gemm_nt<<<dim3(8, NN / 64), 256>>>(p_xbn, W1, p_xw, NN, 512, 128, 0);
    gemm_nt<<<dim3(8, EE / 64), 256>>>(p_ef, W1, p_ew, EE, 512, 128, 0);
    rowdot<<<NN, 128>>>(p_xw, att1, 256, NHEADS, p_xa);
    rowdot<<<EE, 128>>>(p_ew, att1 + 128, 256, NHEADS, p_ea);
    zero_k<<<128, 256>>>(p_smax, NN * NHEADS);
    zero_k<<<128, 256>>>(p_ssum, NN * NHEADS);
    alpha_max<<<NZ * NHEADS / 256, 256>>>(e0, e1, p_xa, p_ea, NHEADS);
    alpha_exp<<<NZ * NHEADS / 256, 256>>>(e0, NHEADS);
    alpha_norm<<<NZ * NHEADS / 256, 256>>>(e0, NHEADS);
    eout_gather<NHEADS><<<EE, 128>>>(e0, p_xw);
    node_out<NHEADS><<<NN, 128>>>(e1, bias1, p_x1);

    // ---- conv 2 (1 head) ----
    efeat<<<EE, 128>>>(e0, p_x1, p_ef);
    gemm_nt<<<dim3(2, NN / 64), 256>>>(p_x1, W2, p_xw, NN, 128, 128, 0);
    gemm_nt<<<dim3(2, EE / 64), 256>>>(p_ef, W2, p_ew, EE, 128, 128, 0);
    rowdot<<<NN, 32>>>(p_xw, att2, 256, 1, p_xa);
    rowdot<<<EE, 32>>>(p_ew, att2 + 128, 256, 1, p_ea);
    zero_k<<<32, 256>>>(p_smax, NN);
    zero_k<<<32, 256>>>(p_ssum, NN);
    alpha_max<<<NZ / 256, 256>>>(e0, e1, p_xa, p_ea, 1);
    alpha_exp<<<NZ / 256, 256>>>(e0, 1);
    alpha_norm<<<NZ / 256, 256>>>(e0, 1);
    eout_gather<1><<<EE, 128>>>(e0, p_xw);
    node_out<1><<<NN, 128>>>(e1, bias2, out_x);

    // ---- head ----
    head_k<<<NN / 4, 128>>>(out_x, Wo, bo, out_o);
}

// round 8
// speedup vs baseline: 1.3690x; 1.3690x over previous
#include <cuda_runtime.h>
#include <math.h>

#define NN 8192
#define TT 32
#define FF 16
#define HH 128
#define NHEADS 4
#define EE 2048
#define NZ 65536
#define NH (NN*HH)

// ----------------- static device scratch (no allocs) -----------------
__device__ float g_scale1[512], g_shift1[512], g_sum1[512], g_sq1[512];
__device__ float g_scale2[HH], g_shift2[HH], g_sum2[HH], g_sq2[HH];
__device__ float g_WhhT[384 * HH];
__device__ float g_h0[NH], g_h1[NH];
__device__ float g_ctx[NN * TT * HH];
__device__ float g_q[NH];
__device__ float g_comb[NN * 2 * HH];
__device__ float g_xbn[NH];
__device__ float g_ef[EE * HH];
__device__ float g_xw[NN * 512];
__device__ float g_ew[EE * 512];
__device__ float g_xa[NN * NHEADS];
__device__ float g_ea[EE * NHEADS];
__device__ float g_alpha[NZ * NHEADS];
__device__ unsigned g_segmax[NN * NHEADS];
__device__ float g_segsum[NN * NHEADS];
__device__ float g_Dinv[NN];
__device__ float g_eout[EE * NHEADS * HH];
__device__ float g_x1[NH];
__device__ int g_cnt[NN], g_cursor[NN], g_rowptr[NN + 1], g_adj[NZ];

// ----------------- helpers -----------------
__device__ __forceinline__ unsigned fenc(float a) {
    unsigned u = __float_as_uint(a);
    return (u & 0x80000000u) ? ~u : (u | 0x80000000u);
}
__device__ __forceinline__ float fdec(unsigned u) {
    return (u & 0x80000000u) ? __uint_as_float(u & 0x7FFFFFFFu) : __uint_as_float(~u);
}
__device__ __forceinline__ float sigmf(float x) { return 1.f / (1.f + expf(-x)); }

__global__ void zero_k(float* p, int n) {
    for (int i = blockIdx.x * blockDim.x + threadIdx.x; i < n; i += gridDim.x * blockDim.x)
        p[i] = 0.f;
}

// ----------------- batchnorm (atomic-free one-shot stats) -----------------
// grid.x = ncols/32, block = 1024 (32 cols x 32 row-groups)
__global__ void bn_stats(const float* __restrict__ x, int ncols, float* sum, float* sq) {
    __shared__ float ssum[32 * 33], ssq[32 * 33];
    int c = threadIdx.x & 31, rg = threadIdx.x >> 5;
    int col = blockIdx.x * 32 + c;
    float s = 0.f, q = 0.f;
    for (int r = rg; r < NN; r += 32) {
        float v = x[(size_t)r * ncols + col];
        s += v; q += v * v;
    }
    ssum[rg * 33 + c] = s; ssq[rg * 33 + c] = q;
    __syncthreads();
    if (threadIdx.x < 32) {
        float S = 0.f, Q = 0.f;
        for (int g = 0; g < 32; g++) { S += ssum[g * 33 + threadIdx.x]; Q += ssq[g * 33 + threadIdx.x]; }
        sum[blockIdx.x * 32 + threadIdx.x] = S;
        sq[blockIdx.x * 32 + threadIdx.x] = Q;
    }
}
__global__ void bn_finalize(const float* sum, const float* sq, const float* g,
                            const float* b, float* scale, float* shift, int ncols) {
    int c = blockIdx.x * blockDim.x + threadIdx.x;
    if (c >= ncols) return;
    float m = sum[c] * (1.f / NN);
    float v = sq[c] * (1.f / NN) - m * m;
    float sc = rsqrtf(v + 1e-5f) * g[c];
    scale[c] = sc; shift[c] = b[c] - m * sc;
}
__global__ void bn_apply(const float* __restrict__ x, const float* scale,
                         const float* shift, float* y) {
    int i = blockIdx.x * blockDim.x + threadIdx.x;
    if (i >= NH) return;
    int c = i & (HH - 1);
    y[i] = x[i] * scale[c] + shift[c];
}

// ----------------- GRU -----------------
// prep: transpose Whh(384,128) -> WhhT[k*384+row], zero h0
__global__ void gru_prep(const float* __restrict__ Whh, float* WhhT, float* h0) {
    int i = blockIdx.x * blockDim.x + threadIdx.x;
    if (i < 384 * 128) { int r = i >> 7, k = i & 127; WhhT[k * 384 + r] = Whh[i]; }
    for (int j = i; j < NH; j += gridDim.x * blockDim.x) h0[j] = 0.f;
}

// grid (NN/256, 4), block 512, dynamic smem 208640 B. One block per SM, FFMA-bound.
// Block: 256 nodes x 32 hidden cols. Thread: lane jj = col, warp = 16-node slab.
#define SH_PAD 132
#define SMEM_GRU ((256*SH_PAD + 3*128*32 + 256*17 + 16*96 + 192) * 4)
__global__ void __launch_bounds__(512)
gru_step(const float* __restrict__ price,
         const float* __restrict__ Wih, const float* __restrict__ bih,
         const float* __restrict__ bhh,
         const float* __restrict__ h_in, float* __restrict__ h_out, int t) {
    extern __shared__ float smem[];
    float* sh   = smem;                       // 256 x 132
    float* sW   = sh + 256 * SH_PAD;          // [g*128+k][32]
    float* sx   = sW + 3 * 128 * 32;          // 256 x 17
    float* sWih = sx + 256 * 17;              // [f][96]
    float* sb   = sWih + 16 * 96;             // bih 96 | bhh 96

    int tid = threadIdx.x;
    int node0 = blockIdx.x * 256, jtile = blockIdx.y * 32;

    // h tile: 8192 float4 loads
    for (int idx = tid; idx < 8192; idx += 512) {
        int nd = idx >> 5, q = idx & 31;
        float4 v = *(const float4*)&h_in[(node0 + nd) * HH + q * 4];
        *(float4*)&sh[nd * SH_PAD + q * 4] = v;
    }
    // W slab: 3072 float4
    for (int idx = tid; idx < 3072; idx += 512) {
        int gk = idx >> 3, q = idx & 7;
        int g = gk >> 7, k = gk & 127;
        float4 v = *(const float4*)&g_WhhT[k * 384 + g * 128 + jtile + q * 4];
        *(float4*)&sW[gk * 32 + q * 4] = v;
    }
    // x tile (bn applied)
    for (int idx = tid; idx < 4096; idx += 512) {
        int nd = idx >> 4, f = idx & 15, col = t * 16 + f;
        sx[nd * 17 + f] = price[(size_t)(node0 + nd) * 512 + col] * g_scale1[col] + g_shift1[col];
    }
    // Wih slab
    for (int idx = tid; idx < 1536; idx += 512) {
        int r = idx >> 4, f = idx & 15;
        sWih[f * 96 + r] = Wih[((r >> 5) * 128 + jtile + (r & 31)) * 16 + f];
    }
    if (tid < 96) {
        int g = tid >> 5, jj = tid & 31;
        sb[tid] = bih[g * 128 + jtile + jj];
        sb[96 + tid] = bhh[g * 128 + jtile + jj];
    }
    __syncthreads();

    int jj = tid & 31, nbase = (tid >> 5) * 16;
    float aR[16], aZ[16], aNx[16], aNh[16];
    {
        float br = sb[jj] + sb[96 + jj];
        float bz = sb[32 + jj] + sb[96 + 32 + jj];
        float bnx = sb[64 + jj], bnh = sb[96 + 64 + jj];
#pragma unroll
        for (int i = 0; i < 16; i++) { aR[i] = br; aZ[i] = bz; aNx[i] = bnx; aNh[i] = bnh; }
    }

    // recurrence: k in quads
    for (int k = 0; k < 128; k += 4) {
        float w0x = sW[(k+0)*32+jj], w0y = sW[(k+1)*32+jj], w0z = sW[(k+2)*32+jj], w0w = sW[(k+3)*32+jj];
        float w1x = sW[(128+k)*32+jj], w1y = sW[(129+k)*32+jj], w1z = sW[(130+k)*32+jj], w1w = sW[(131+k)*32+jj];
        float w2x = sW[(256+k)*32+jj], w2y = sW[(257+k)*32+jj], w2z = sW[(258+k)*32+jj], w2w = sW[(259+k)*32+jj];
#pragma unroll
        for (int i = 0; i < 16; i++) {
            float4 hv = *(const float4*)&sh[(nbase + i) * SH_PAD + k];
            aR[i]  += hv.x*w0x + hv.y*w0y + hv.z*w0z + hv.w*w0w;
            aZ[i]  += hv.x*w1x + hv.y*w1y + hv.z*w1z + hv.w*w1w;
            aNh[i] += hv.x*w2x + hv.y*w2y + hv.z*w2z + hv.w*w2w;
        }
    }
    // input part
#pragma unroll
    for (int f = 0; f < 16; f++) {
        float u0 = sWih[f*96+jj], u1 = sWih[f*96+32+jj], u2 = sWih[f*96+64+jj];
#pragma unroll
        for (int i = 0; i < 16; i++) {
            float xv = sx[(nbase + i) * 17 + f];
            aR[i] += xv*u0; aZ[i] += xv*u1; aNx[i] += xv*u2;
        }
    }
    int j = jtile + jj;
#pragma unroll
    for (int i = 0; i < 16; i++) {
        int nd = nbase + i;
        float r = sigmf(aR[i]), z = sigmf(aZ[i]);
        float nv = tanhf(aNx[i] + r * aNh[i]);
        float hnew = (1.f - z) * nv + z * sh[nd * SH_PAD + j];
        int gn = node0 + nd;
        h_out[gn * HH + j] = hnew;
        g_ctx[(size_t)gn * (TT * HH) + t * HH + j] = hnew;
    }
}

// ----------------- generic NT sgemm: C = act(A(M,K) @ B(Nc,K)^T) -----------------
__global__ void gemm_nt(const float* __restrict__ A, const float* __restrict__ B,
                        float* __restrict__ C, int M, int Nc, int K, int act) {
    __shared__ float As[16 * 68], Bs[16 * 68];
    int tid = threadIdx.x, n0 = blockIdx.x * 64, m0 = blockIdx.y * 64;
    int lrow = tid >> 2, kq = tid & 3, tx = tid & 15, ty = tid >> 4;
    float c[4][4];
#pragma unroll
    for (int i = 0; i < 4; i++)
#pragma unroll
        for (int jv = 0; jv < 4; jv++) c[i][jv] = 0.f;

    for (int k0 = 0; k0 < K; k0 += 16) {
        float4 av = *(const float4*)&A[(size_t)(m0 + lrow) * K + k0 + kq * 4];
        float4 bv = *(const float4*)&B[(size_t)(n0 + lrow) * K + k0 + kq * 4];
        __syncthreads();
        As[(kq*4+0)*68+lrow] = av.x; As[(kq*4+1)*68+lrow] = av.y;
        As[(kq*4+2)*68+lrow] = av.z; As[(kq*4+3)*68+lrow] = av.w;
        Bs[(kq*4+0)*68+lrow] = bv.x; Bs[(kq*4+1)*68+lrow] = bv.y;
        Bs[(kq*4+2)*68+lrow] = bv.z; Bs[(kq*4+3)*68+lrow] = bv.w;
        __syncthreads();
#pragma unroll
        for (int kk = 0; kk < 16; kk++) {
            float4 a = *(const float4*)&As[kk * 68 + ty * 4];
            float4 b = *(const float4*)&Bs[kk * 68 + tx * 4];
            float ar[4] = {a.x, a.y, a.z, a.w}, br[4] = {b.x, b.y, b.z, b.w};
#pragma unroll
            for (int i = 0; i < 4; i++)
#pragma unroll
                for (int jv = 0; jv < 4; jv++) c[i][jv] += ar[i] * br[jv];
        }
    }
#pragma unroll
    for (int i = 0; i < 4; i++)
#pragma unroll
        for (int jv = 0; jv < 4; jv++) {
            float v = c[i][jv];
            if (act == 1) v = tanhf(v);
            C[(size_t)(m0 + ty * 4 + i) * Nc + n0 + tx * 4 + jv] = v;
        }
}

// ----------------- temporal attention middle -----------------
__global__ void attn_mid(const float* __restrict__ ae, const float* __restrict__ ab) {
    __shared__ float sctx[32 * 129], sq[128], sw[32], sbt[32];
    int n = blockIdx.x, tid = threadIdx.x;
    sq[tid] = g_q[n * HH + tid];
    for (int idx = tid; idx < TT * HH; idx += 128) {
        int t = idx >> 7, k = idx & 127;
        sctx[t * 129 + k] = g_ctx[(size_t)n * (TT * HH) + idx];
    }
    __syncthreads();
    if (tid < 32) {
        float s = 0.f;
        for (int k = 0; k < 128; k++) s += sq[k] * sctx[tid * 129 + k];
        float m = s;
#pragma unroll
        for (int o = 16; o; o >>= 1) m = fmaxf(m, __shfl_xor_sync(0xffffffffu, m, o));
        float e = expf(s - m), su = e;
#pragma unroll
        for (int o = 16; o; o >>= 1) su += __shfl_xor_sync(0xffffffffu, su, o);
        sw[tid] = e / su;
        sbt[tid] = expf(-ab[n] * (float)(31 - tid));
    }
    __syncthreads();
    float aen = ae[n], acc = 0.f;
#pragma unroll 4
    for (int t = 0; t < TT; t++) {
        float mx = sw[t] * sctx[t * 129 + tid];
        acc += mx + fmaxf(aen * mx * sbt[t], 0.f);
    }
    g_comb[n * 256 + tid] = acc;
    g_comb[n * 256 + 128 + tid] = sq[tid];
}

// ----------------- CSR build (by src) -----------------
__global__ void count_src(const int* __restrict__ e0, int* cnt) {
    int i = blockIdx.x * blockDim.x + threadIdx.x;
    if (i < NZ) atomicAdd(&cnt[e0[i]], 1);
}
__global__ void scan_csr(const int* __restrict__ cnt, int* rowptr, float* Dinv) {
    __shared__ int s[1024];
    int tid = threadIdx.x, base = tid * 8, loc[8], sum = 0;
#pragma unroll
    for (int j = 0; j < 8; j++) { loc[j] = sum; sum += cnt[base + j]; }
    s[tid] = sum;
    __syncthreads();
    for (int off = 1; off < 1024; off <<= 1) {
        int v = (tid >= off) ? s[tid - off] : 0;
        __syncthreads();
        s[tid] += v;
        __syncthreads();
    }
    int excl = tid ? s[tid - 1] : 0;
#pragma unroll
    for (int j = 0; j < 8; j++) {
        rowptr[base + j] = excl + loc[j];
        int c = cnt[base + j];
        Dinv[base + j] = c ? 1.f / (float)c : 0.f;
    }
    if (tid == 1023) rowptr[NN] = s[1023];
}
__global__ void fill_csr(const int* __restrict__ e0, const int* __restrict__ rowptr,
                         int* cursor, int* adj) {
    int i = blockIdx.x * blockDim.x + threadIdx.x;
    if (i >= NZ) return;
    int sg = e0[i];
    int p = atomicAdd(&cursor[sg], 1);
    adj[rowptr[sg] + p] = i;
}

// ----------------- hypergraph pieces -----------------
__global__ void efeat(const int* __restrict__ e0, const float* __restrict__ x, float* ef) {
    int d = blockIdx.x, c = threadIdx.x;
    float a = 0.f;
#pragma unroll 4
    for (int j = 0; j < 32; j++) a += x[e0[d + j * EE] * HH + c];
    ef[d * HH + c] = a;
}

__global__ void rowdot(const float* __restrict__ xw, const float* __restrict__ att,
                       int stride, int heads, float* __restrict__ out) {
    int r = blockIdx.x, h = threadIdx.x >> 5, lane = threadIdx.x & 31;
    const float* row = xw + (size_t)(r * heads + h) * HH;
    float s = 0.f;
#pragma unroll
    for (int m = 0; m < 4; m++) s += row[lane + 32 * m] * att[h * stride + lane + 32 * m];
#pragma unroll
    for (int o = 16; o; o >>= 1) s += __shfl_xor_sync(0xffffffffu, s, o);
    if (!lane) out[r * heads + h] = s;
}

__global__ void alpha_max(const int* __restrict__ e0, const int* __restrict__ e1,
                          const float* __restrict__ xa, const float* __restrict__ ea,
                          int heads) {
    int g = blockIdx.x * blockDim.x + threadIdx.x;
    if (g >= NZ * heads) return;
    int i = g / heads, h = g - i * heads;
    float a = xa[e0[i] * heads + h] + ea[e1[i] * heads + h];
    a = (a > 0.f) ? a : 0.2f * a;
    g_alpha[g] = a;
    atomicMax(&g_segmax[e0[i] * heads + h], fenc(a));
}
__global__ void alpha_exp(const int* __restrict__ e0, int heads) {
    int g = blockIdx.x * blockDim.x + threadIdx.x;
    if (g >= NZ * heads) return;
    int i = g / heads, h = g - i * heads;
    float ex = expf(g_alpha[g] - fdec(g_segmax[e0[i] * heads + h]));
    g_alpha[g] = ex;
    atomicAdd(&g_segsum[e0[i] * heads + h], ex);
}

// eout[d,h,:] = (1/32) * sum_j alpha_norm[d+jE,h] * xw[e0[d+jE],h,:]
template <int HT>
__global__ void eout_gather(const int* __restrict__ e0, const float* __restrict__ xw) {
    int d = blockIdx.x, c = threadIdx.x;
    float acc[HT];
#pragma unroll
    for (int h = 0; h < HT; h++) acc[h] = 0.f;
    for (int j = 0; j < 32; j++) {
        int i = d + j * EE, s = e0[i];
#pragma unroll
        for (int h = 0; h < HT; h++) {
            float an = g_alpha[i * HT + h] / (g_segsum[s * HT + h] + 1e-16f);
            acc[h] += an * xw[(size_t)(s * HT + h) * HH + c];
        }
    }
#pragma unroll
    for (int h = 0; h < HT; h++)
        g_eout[(size_t)(d * HT + h) * HH + c] = acc[h] * (1.f / 32.f);
}

template <int HT>
__global__ void node_out(const int* __restrict__ e1, const float* __restrict__ bias,
                         float* __restrict__ out) {
    int s = blockIdx.x, c = threadIdx.x;
    int b = g_rowptr[s], e = g_rowptr[s + 1];
    float ssv[HT];
#pragma unroll
    for (int h = 0; h < HT; h++) ssv[h] = g_segsum[s * HT + h] + 1e-16f;
    float a[HT];
#pragma unroll
    for (int h = 0; h < HT; h++) a[h] = 0.f;
    for (int k = b; k < e; k++) {
        int i = g_adj[k], d = e1[i];
#pragma unroll
        for (int h = 0; h < HT; h++)
            a[h] += (g_alpha[i * HT + h] / ssv[h]) * g_eout[(size_t)(d * HT + h) * HH + c];
    }
    float v = 0.f;
#pragma unroll
    for (int h = 0; h < HT; h++) v += a[h];
    v = v * g_Dinv[s] * (1.f / HT) + bias[c];
    out[s * HH + c] = (v > 0.f) ? v : 0.2f * v;
}

__global__ void head_k(const float* __restrict__ x2, const float* __restrict__ Wo,
                       const float* __restrict__ bo, float* __restrict__ out) {
    int n = blockIdx.x * 4 + (threadIdx.x >> 5), lane = threadIdx.x & 31;
    float s = 0.f;
#pragma unroll
    for (int m = 0; m < 4; m++) s += x2[n * HH + lane + 32 * m] * Wo[lane + 32 * m];
#pragma unroll
    for (int o = 16; o; o >>= 1) s += __shfl_xor_sync(0xffffffffu, s, o);
    if (!lane) {
        float v = s + bo[0];
        out[n] = (v > 0.f) ? v : 0.01f * v;
    }
}

// ----------------- host -----------------
static void* sym(const void* s) { void* p = 0; cudaGetSymbolAddress(&p, s); return p; }

extern "C" void kernel_launch(void* const* d_in, const int* in_sizes, int n_in,
                              void* d_out, int out_size) {
    const float* price = (const float*)d_in[0];
    const int*   e     = (const int*)d_in[1];
    const float* bn1g  = (const float*)d_in[2];
    const float* bn1b  = (const float*)d_in[3];
    const float* Wih   = (const float*)d_in[4];
    const float* Whh   = (const float*)d_in[5];
    const float* bih   = (const float*)d_in[6];
    const float* bhh   = (const float*)d_in[7];
    const float* Wq    = (const float*)d_in[8];
    const float* Wout  = (const float*)d_in[9];
    const float* ae    = (const float*)d_in[10];
    const float* ab    = (const float*)d_in[11];
    const float* bn2g  = (const float*)d_in[12];
    const float* bn2b  = (const float*)d_in[13];
    const float* W1    = (const float*)d_in[14];
    const float* att1  = (const float*)d_in[15];
    const float* bias1 = (const float*)d_in[16];
    const float* W2    = (const float*)d_in[17];
    const float* att2  = (const float*)d_in[18];
    const float* bias2 = (const float*)d_in[19];
    const float* Wo    = (const float*)d_in[20];
    const float* bo    = (const float*)d_in[21];
    const int* e0 = e;
    const int* e1 = e + NZ;

    float* out_nf = (float*)d_out;
    float* out_x  = out_nf + NH;
    float* out_o  = out_x + NH;

    float* p_sum1 = (float*)sym(g_sum1);   float* p_sq1 = (float*)sym(g_sq1);
    float* p_sum2 = (float*)sym(g_sum2);   float* p_sq2 = (float*)sym(g_sq2);
    float* p_sc1 = (float*)sym(g_scale1);  float* p_sh1 = (float*)sym(g_shift1);
    float* p_sc2 = (float*)sym(g_scale2);  float* p_sh2 = (float*)sym(g_shift2);
    float* p_h0 = (float*)sym(g_h0);       float* p_h1 = (float*)sym(g_h1);
    float* p_q = (float*)sym(g_q);         float* p_comb = (float*)sym(g_comb);
    float* p_xbn = (float*)sym(g_xbn);     float* p_ef = (float*)sym(g_ef);
    float* p_xw = (float*)sym(g_xw);       float* p_ew = (float*)sym(g_ew);
    float* p_xa = (float*)sym(g_xa);       float* p_ea = (float*)sym(g_ea);
    float* p_smax = (float*)sym(g_segmax); float* p_ssum = (float*)sym(g_segsum);
    float* p_x1 = (float*)sym(g_x1);       float* p_whhT = (float*)sym(g_WhhT);
    int* p_cnt = (int*)sym(g_cnt);         int* p_cur = (int*)sym(g_cursor);
    int* p_rp = (int*)sym(g_rowptr);       int* p_adj = (int*)sym(g_adj);
    float* p_Dinv = (float*)sym(g_Dinv);

    cudaFuncSetAttribute(gru_step, cudaFuncAttributeMaxDynamicSharedMemorySize, SMEM_GRU);

    // launches 1-3 so launch #4 (= global #6, ncu's -s 5 -c 1 target) is gru_step
    bn_stats<<<16, 1024>>>(price, 512, p_sum1, p_sq1);
    bn_finalize<<<4, 128>>>(p_sum1, p_sq1, bn1g, bn1b, p_sc1, p_sh1, 512);
    gru_prep<<<2048, 512>>>(Whh, p_whhT, p_h0);

    for (int t = 0; t < TT; t++) {
        float* hi = (t & 1) ? p_h1 : p_h0;
        float* ho = (t & 1) ? p_h0 : p_h1;
        gru_step<<<dim3(NN / 256, 4), 512, SMEM_GRU>>>(price, Wih, bih, bhh, hi, ho, t);
    }
    // hT in g_h0

    gemm_nt<<<dim3(2, NN / 64), 256>>>(p_h0, Wq, p_q, NN, 128, 128, 0);
    attn_mid<<<NN, 128>>>(ae, ab);
    gemm_nt<<<dim3(2, NN / 64), 256>>>(p_comb, Wout, out_nf, NN, 128, 256, 1);

    bn_stats<<<4, 1024>>>(out_nf, 128, p_sum2, p_sq2);
    bn_finalize<<<1, 128>>>(p_sum2, p_sq2, bn2g, bn2b, p_sc2, p_sh2, 128);
    bn_apply<<<NH / 256, 256>>>(out_nf, p_sc2, p_sh2, p_xbn);

    // CSR by src
    zero_k<<<16, 256>>>((float*)p_cnt, NN);
    count_src<<<NZ / 256, 256>>>(e0, p_cnt);
    scan_csr<<<1, 1024>>>(p_cnt, p_rp, p_Dinv);
    zero_k<<<16, 256>>>((float*)p_cur, NN);
    fill_csr<<<NZ / 256, 256>>>(e0, p_rp, p_cur, p_adj);

    // ---- conv 1 (4 heads) ----
    efeat<<<EE, 128>>>(e0, p_xbn, p_ef);
    gemm_nt<<<dim3(8, NN / 64), 256>>>(p_xbn, W1, p_xw, NN, 512, 128, 0);
    gemm_nt<<<dim3(8, EE / 64), 256>>>(p_ef, W1, p_ew, EE, 512, 128, 0);
    rowdot<<<NN, 128>>>(p_xw, att1, 256, NHEADS, p_xa);
    rowdot<<<EE, 128>>>(p_ew, att1 + 128, 256, NHEADS, p_ea);
    zero_k<<<128, 256>>>(p_smax, NN * NHEADS);
    zero_k<<<128, 256>>>(p_ssum, NN * NHEADS);
    alpha_max<<<NZ * NHEADS / 256, 256>>>(e0, e1, p_xa, p_ea, NHEADS);
    alpha_exp<<<NZ * NHEADS / 256, 256>>>(e0, NHEADS);
    eout_gather<NHEADS><<<EE, 128>>>(e0, p_xw);
    node_out<NHEADS><<<NN, 128>>>(e1, bias1, p_x1);

    // ---- conv 2 (1 head) ----
    efeat<<<EE, 128>>>(e0, p_x1, p_ef);
    gemm_nt<<<dim3(2, NN / 64), 256>>>(p_x1, W2, p_xw, NN, 128, 128, 0);
    gemm_nt<<<dim3(2, EE / 64), 256>>>(p_ef, W2, p_ew, EE, 128, 128, 0);
    rowdot<<<NN, 32>>>(p_xw, att2, 256, 1, p_xa);
    rowdot<<<EE, 32>>>(p_ew, att2 + 128, 256, 1, p_ea);
    zero_k<<<32, 256>>>(p_smax, NN);
    zero_k<<<32, 256>>>(p_ssum, NN);
    alpha_max<<<NZ / 256, 256>>>(e0, e1, p_xa, p_ea, 1);
    alpha_exp<<<NZ / 256, 256>>>(e0, 1);
    eout_gather<1><<<EE, 128>>>(e0, p_xw);
    node_out<1><<<NN, 128>>>(e1, bias2, out_x);

    head_k<<<NN / 4, 128>>>(out_x, Wo, bo, out_o);
}

// round 11
// speedup vs baseline: 2.5414x; 1.8564x over previous
#include <cuda_runtime.h>
#include <math.h>

#define NN 8192
#define TT 32
#define FF 16
#define HH 128
#define NHEADS 4
#define EE 2048
#define NZ 65536
#define NH (NN*HH)

// ----------------- static device scratch (no allocs) -----------------
__device__ float g_scale1[512], g_shift1[512], g_sum1[512], g_sq1[512];
__device__ float g_scale2[HH], g_shift2[HH], g_sum2[HH], g_sq2[HH];
__device__ float g_WfragH[64 * 16 * 32 * 2];       // tf32 B-frags, h-part (256KB)
__device__ float g_WfragX[32 * 64 * 2 * 32 * 2];   // tf32 B-frags, x-part per t (1MB)
__device__ float g_bias[32 * 512];                 // combined per-t bias
__device__ float g_h0[NH];
__device__ float g_ctx[NN * TT * HH];
__device__ float g_q[NH];
__device__ float g_comb[NN * 2 * HH];
__device__ float g_xbn[NH];
__device__ float g_ef[EE * HH];
__device__ float g_xw[NN * 512];
__device__ float g_ew[EE * 512];
__device__ float g_xa[NN * NHEADS];
__device__ float g_ea[EE * NHEADS];
__device__ float g_alpha[NZ * NHEADS];
__device__ unsigned g_segmax[NN * NHEADS];
__device__ float g_segsum[NN * NHEADS];
__device__ float g_Dinv[NN];
__device__ float g_eout[EE * NHEADS * HH];
__device__ float g_x1[NH];
__device__ int g_cnt[NN], g_cursor[NN], g_rowptr[NN + 1], g_adj[NZ];

// ----------------- helpers -----------------
__device__ __forceinline__ unsigned fenc(float a) {
    unsigned u = __float_as_uint(a);
    return (u & 0x80000000u) ? ~u : (u | 0x80000000u);
}
__device__ __forceinline__ float fdec(unsigned u) {
    return (u & 0x80000000u) ? __uint_as_float(u & 0x7FFFFFFFu) : __uint_as_float(~u);
}
__device__ __forceinline__ float tf32r(float x) {
    unsigned u; asm("cvt.rna.tf32.f32 %0, %1;" : "=r"(u) : "f"(x));
    return __uint_as_float(u);
}
__device__ __forceinline__ float sigacc(float x) {
    return __fdividef(1.f, 1.f + __expf(-x));
}
__device__ __forceinline__ float tanhacc(float x) {
    return 1.f - __fdividef(2.f, __expf(2.f * x) + 1.f);
}
__device__ __forceinline__ void mma8(float* c, const unsigned* a, unsigned b0, unsigned b1) {
    asm volatile(
        "mma.sync.aligned.m16n8k8.row.col.f32.tf32.tf32.f32 "
        "{%0,%1,%2,%3}, {%4,%5,%6,%7}, {%8,%9}, {%0,%1,%2,%3};\n"
        : "+f"(c[0]), "+f"(c[1]), "+f"(c[2]), "+f"(c[3])
        : "r"(a[0]), "r"(a[1]), "r"(a[2]), "r"(a[3]), "r"(b0), "r"(b1));
}

__global__ void zero_k(float* p, int n) {
    for (int i = blockIdx.x * blockDim.x + threadIdx.x; i < n; i += gridDim.x * blockDim.x)
        p[i] = 0.f;
}

// ----------------- batchnorm -----------------
__global__ void bn_stats(const float* __restrict__ x, int ncols, float* sum, float* sq) {
    __shared__ float ssum[32 * 33], ssq[32 * 33];
    int c = threadIdx.x & 31, rg = threadIdx.x >> 5;
    int col = blockIdx.x * 32 + c;
    float s = 0.f, q = 0.f;
    for (int r = rg; r < NN; r += 32) {
        float v = x[(size_t)r * ncols + col];
        s += v; q += v * v;
    }
    ssum[rg * 33 + c] = s; ssq[rg * 33 + c] = q;
    __syncthreads();
    if (threadIdx.x < 32) {
        float S = 0.f, Q = 0.f;
        for (int g = 0; g < 32; g++) { S += ssum[g * 33 + threadIdx.x]; Q += ssq[g * 33 + threadIdx.x]; }
        sum[blockIdx.x * 32 + threadIdx.x] = S;
        sq[blockIdx.x * 32 + threadIdx.x] = Q;
    }
}
__global__ void bn_finalize(const float* sum, const float* sq, const float* g,
                            const float* b, float* scale, float* shift, int ncols) {
    int c = blockIdx.x * blockDim.x + threadIdx.x;
    if (c >= ncols) return;
    float m = sum[c] * (1.f / NN);
    float v = sq[c] * (1.f / NN) - m * m;
    float sc = rsqrtf(v + 1e-5f) * g[c];
    scale[c] = sc; shift[c] = b[c] - m * sc;
}
__global__ void bn_apply(const float* __restrict__ x, const float* scale,
                         const float* shift, float* y) {
    int i = blockIdx.x * blockDim.x + threadIdx.x;
    if (i >= NH) return;
    int c = i & (HH - 1);
    y[i] = x[i] * scale[c] + shift[c];
}

// ----------------- GRU prep: fragment-ready tf32 weights + biases -----------------
// Combined gate matrix: 512 cols, c = 4j+p (p: 0=r,1=z,2=nx,3=nh), K=144 ([h 0..127 | x f 0..15])
// h-part rows: r/z/nh from Whh, nx = 0.  x-part: r/z/nx from Wih*scale1(t), nh = 0.
__global__ void prep_all(const float* __restrict__ Whh, const float* __restrict__ Wih,
                         const float* __restrict__ bih, const float* __restrict__ bhh) {
    int b = blockIdx.x, tid = threadIdx.x;
    if (b < 128) {                       // WfragH: [ntg 64][ks 16][lane 32][2]
        int idx = b * 256 + tid;
        int lane = idx & 31, ks = (idx >> 5) & 15, ntg = idx >> 9;
        int k = ks * 8 + (lane & 3), c = ntg * 8 + (lane >> 2);
        int j = c >> 2, p = c & 3;
        float b0 = 0.f, b1 = 0.f;
        if (p != 2) {
            int g = (p == 3) ? (256 + j) : (p * 128 + j);
            b0 = Whh[g * 128 + k]; b1 = Whh[g * 128 + k + 4];
        }
        g_WfragH[idx * 2] = tf32r(b0); g_WfragH[idx * 2 + 1] = tf32r(b1);
    } else if (b < 640) {                // WfragX: [t 32][ntg 64][ks2 2][lane 32][2]
        int idx = (b - 128) * 256 + tid;
        int lane = idx & 31, ks2 = (idx >> 5) & 1, ntg = (idx >> 6) & 63, t = idx >> 12;
        int f = ks2 * 8 + (lane & 3), c = ntg * 8 + (lane >> 2);
        int j = c >> 2, p = c & 3;
        float b0 = 0.f, b1 = 0.f;
        if (p != 3) {
            int g = p * 128 + j;
            b0 = Wih[g * 16 + f] * g_scale1[t * 16 + f];
            b1 = Wih[g * 16 + f + 4] * g_scale1[t * 16 + f + 4];
        }
        g_WfragX[idx * 2] = tf32r(b0); g_WfragX[idx * 2 + 1] = tf32r(b1);
    } else {                             // bias: [t 32][c 512]
        int idx = (b - 640) * 256 + tid;
        int c = idx & 511, t = idx >> 9;
        int j = c >> 2, p = c & 3;
        float v;
        if (p == 3) v = bhh[256 + j];
        else {
            int g = p * 128 + j;
            float sd = 0.f;
            for (int f = 0; f < 16; f++) sd += g_shift1[t * 16 + f] * Wih[g * 16 + f];
            v = bih[g] + sd + ((p < 2) ? bhh[g] : 0.f);
        }
        g_bias[t * 512 + c] = v;
    }
}

// ----------------- persistent tf32-mma GRU -----------------
// grid 128 blocks x 256 threads. Block owns 64 nodes; h tile persists in smem across 32 steps.
// Warp w computes cols [w*64, w*64+64); warp tile m64 x n64, 18 k-steps of k8.
#define GPAD 132
__global__ void __launch_bounds__(256)
gru_persist(const float* __restrict__ price) {
    __shared__ float sh[64 * GPAD];
    __shared__ float sx[64 * 20];
    __shared__ float sbias[512];
    int tid = threadIdx.x, lane = tid & 31, warp = tid >> 5;
    int gid = lane >> 2, q = lane & 3;
    int node0 = blockIdx.x * 64;

    for (int i = tid; i < 64 * GPAD; i += 256) sh[i] = 0.f;
    __syncthreads();

    const float2* __restrict__ WH = (const float2*)g_WfragH;

    for (int t = 0; t < TT; t++) {
        // stage x tile (tf32) + bias
        for (int i = tid; i < 1024; i += 256) {
            int nd = i >> 4, f = i & 15;
            sx[nd * 20 + f] = tf32r(price[(size_t)(node0 + nd) * 512 + t * 16 + f]);
        }
        for (int i = tid; i < 512; i += 256) sbias[i] = g_bias[t * 512 + i];
        __syncthreads();   // A

        const float2* __restrict__ WXt = (const float2*)g_WfragX + (size_t)t * 4096;

        float acc[4][8][4];
#pragma unroll
        for (int mt = 0; mt < 4; mt++)
#pragma unroll
            for (int nt = 0; nt < 8; nt++) {
                int cb = warp * 64 + nt * 8 + 2 * q;
                float2 bv = *(const float2*)&sbias[cb];
                acc[mt][nt][0] = bv.x; acc[mt][nt][1] = bv.y;
                acc[mt][nt][2] = bv.x; acc[mt][nt][3] = bv.y;
            }

        float2 bcur[8], bnxt[8];
#pragma unroll
        for (int nt = 0; nt < 8; nt++)
            bcur[nt] = WH[(((warp * 8 + nt) * 16) + 0) * 32 + lane];

        for (int ks = 0; ks < 18; ks++) {
            // prefetch next B frags
            if (ks < 17) {
                int kn = ks + 1;
                if (kn < 16) {
#pragma unroll
                    for (int nt = 0; nt < 8; nt++)
                        bnxt[nt] = WH[(((warp * 8 + nt) * 16) + kn) * 32 + lane];
                } else {
                    int ks2 = kn - 16;
#pragma unroll
                    for (int nt = 0; nt < 8; nt++)
                        bnxt[nt] = WXt[(((warp * 8 + nt) * 2) + ks2) * 32 + lane];
                }
            }
            // A frags
            unsigned a[4][4];
            if (ks < 16) {
                int base = ks * 8 + q;
#pragma unroll
                for (int mt = 0; mt < 4; mt++) {
                    int r0 = mt * 16 + gid;
                    a[mt][0] = __float_as_uint(sh[r0 * GPAD + base]);
                    a[mt][1] = __float_as_uint(sh[(r0 + 8) * GPAD + base]);
                    a[mt][2] = __float_as_uint(sh[r0 * GPAD + base + 4]);
                    a[mt][3] = __float_as_uint(sh[(r0 + 8) * GPAD + base + 4]);
                }
            } else {
                int base = (ks - 16) * 8 + q;
#pragma unroll
                for (int mt = 0; mt < 4; mt++) {
                    int r0 = mt * 16 + gid;
                    a[mt][0] = __float_as_uint(sx[r0 * 20 + base]);
                    a[mt][1] = __float_as_uint(sx[(r0 + 8) * 20 + base]);
                    a[mt][2] = __float_as_uint(sx[r0 * 20 + base + 4]);
                    a[mt][3] = __float_as_uint(sx[(r0 + 8) * 20 + base + 4]);
                }
            }
#pragma unroll
            for (int nt = 0; nt < 8; nt++) {
                unsigned b0 = __float_as_uint(bcur[nt].x), b1 = __float_as_uint(bcur[nt].y);
#pragma unroll
                for (int mt = 0; mt < 4; mt++) mma8(acc[mt][nt], a[mt], b0, b1);
            }
#pragma unroll
            for (int nt = 0; nt < 8; nt++) bcur[nt] = bnxt[nt];
        }

        __syncthreads();   // B: all smem reads for this step done

        // epilogue: pair lanes (q even holds r,z; q odd holds nx,nh for same j)
#pragma unroll
        for (int mt = 0; mt < 4; mt++)
#pragma unroll
            for (int nt = 0; nt < 8; nt++) {
                float c0 = acc[mt][nt][0], c1 = acc[mt][nt][1];
                float c2 = acc[mt][nt][2], c3 = acc[mt][nt][3];
                float v0 = __shfl_xor_sync(0xffffffffu, c0, 1);
                float v1 = __shfl_xor_sync(0xffffffffu, c1, 1);
                float v2 = __shfl_xor_sync(0xffffffffu, c2, 1);
                float v3 = __shfl_xor_sync(0xffffffffu, c3, 1);
                int cb = warp * 64 + nt * 8 + 2 * q;
                int j = cb >> 2;
                float ra, za, nx, nh; int row;
                if ((q & 1) == 0) { row = mt * 16 + gid;     ra = c0; za = c1; nx = v0; nh = v1; }
                else              { row = mt * 16 + gid + 8; ra = v2; za = v3; nx = c2; nh = c3; }
                float r = sigacc(ra), z = sigacc(za);
                float n = tanhacc(nx + r * nh);
                float hold = sh[row * GPAD + j];
                sh[row * GPAD + j] = tf32r((1.f - z) * n + z * hold);
            }
        __syncthreads();   // C

        // flush h -> ctx (coalesced), and hT at t=31
        size_t cbase = (size_t)node0 * 4096 + (size_t)t * 128;
        for (int i = tid; i < 2048; i += 256) {
            int nd = i >> 5, jq = i & 31;
            float4 v = *(const float4*)&sh[nd * GPAD + jq * 4];
            *(float4*)&g_ctx[cbase + (size_t)nd * 4096 + jq * 4] = v;
            if (t == 31) *(float4*)&g_h0[(size_t)(node0 + nd) * 128 + jq * 4] = v;
        }
    }
}

// ----------------- generic NT sgemm: C = act(A(M,K) @ B(Nc,K)^T) -----------------
__global__ void gemm_nt(const float* __restrict__ A, const float* __restrict__ B,
                        float* __restrict__ C, int M, int Nc, int K, int act) {
    __shared__ float As[16 * 68], Bs[16 * 68];
    int tid = threadIdx.x, n0 = blockIdx.x * 64, m0 = blockIdx.y * 64;
    int lrow = tid >> 2, kq = tid & 3, tx = tid & 15, ty = tid >> 4;
    float c[4][4];
#pragma unroll
    for (int i = 0; i < 4; i++)
#pragma unroll
        for (int jv = 0; jv < 4; jv++) c[i][jv] = 0.f;

    for (int k0 = 0; k0 < K; k0 += 16) {
        float4 av = *(const float4*)&A[(size_t)(m0 + lrow) * K + k0 + kq * 4];
        float4 bv = *(const float4*)&B[(size_t)(n0 + lrow) * K + k0 + kq * 4];
        __syncthreads();
        As[(kq*4+0)*68+lrow] = av.x; As[(kq*4+1)*68+lrow] = av.y;
        As[(kq*4+2)*68+lrow] = av.z; As[(kq*4+3)*68+lrow] = av.w;
        Bs[(kq*4+0)*68+lrow] = bv.x; Bs[(kq*4+1)*68+lrow] = bv.y;
        Bs[(kq*4+2)*68+lrow] = bv.z; Bs[(kq*4+3)*68+lrow] = bv.w;
        __syncthreads();
#pragma unroll
        for (int kk = 0; kk < 16; kk++) {
            float4 a = *(const float4*)&As[kk * 68 + ty * 4];
            float4 b = *(const float4*)&Bs[kk * 68 + tx * 4];
            float ar[4] = {a.x, a.y, a.z, a.w}, br[4] = {b.x, b.y, b.z, b.w};
#pragma unroll
            for (int i = 0; i < 4; i++)
#pragma unroll
                for (int jv = 0; jv < 4; jv++) c[i][jv] += ar[i] * br[jv];
        }
    }
#pragma unroll
    for (int i = 0; i < 4; i++)
#pragma unroll
        for (int jv = 0; jv < 4; jv++) {
            float v = c[i][jv];
            if (act == 1) v = tanhf(v);
            C[(size_t)(m0 + ty * 4 + i) * Nc + n0 + tx * 4 + jv] = v;
        }
}

// ----------------- temporal attention middle -----------------
__global__ void attn_mid(const float* __restrict__ ae, const float* __restrict__ ab) {
    __shared__ float sctx[32 * 129], sq[128], sw[32], sbt[32];
    int n = blockIdx.x, tid = threadIdx.x;
    sq[tid] = g_q[n * HH + tid];
    for (int idx = tid; idx < TT * HH; idx += 128) {
        int t = idx >> 7, k = idx & 127;
        sctx[t * 129 + k] = g_ctx[(size_t)n * (TT * HH) + idx];
    }
    __syncthreads();
    if (tid < 32) {
        float s = 0.f;
        for (int k = 0; k < 128; k++) s += sq[k] * sctx[tid * 129 + k];
        float m = s;
#pragma unroll
        for (int o = 16; o; o >>= 1) m = fmaxf(m, __shfl_xor_sync(0xffffffffu, m, o));
        float e = expf(s - m), su = e;
#pragma unroll
        for (int o = 16; o; o >>= 1) su += __shfl_xor_sync(0xffffffffu, su, o);
        sw[tid] = e / su;
        sbt[tid] = expf(-ab[n] * (float)(31 - tid));
    }
    __syncthreads();
    float aen = ae[n], acc = 0.f;
#pragma unroll 4
    for (int t = 0; t < TT; t++) {
        float mx = sw[t] * sctx[t * 129 + tid];
        acc += mx + fmaxf(aen * mx * sbt[t], 0.f);
    }
    g_comb[n * 256 + tid] = acc;
    g_comb[n * 256 + 128 + tid] = sq[tid];
}

// ----------------- CSR build (by src) -----------------
__global__ void count_src(const int* __restrict__ e0, int* cnt) {
    int i = blockIdx.x * blockDim.x + threadIdx.x;
    if (i < NZ) atomicAdd(&cnt[e0[i]], 1);
}
__global__ void scan_csr(const int* __restrict__ cnt, int* rowptr, float* Dinv) {
    __shared__ int s[1024];
    int tid = threadIdx.x, base = tid * 8, loc[8], sum = 0;
#pragma unroll
    for (int j = 0; j < 8; j++) { loc[j] = sum; sum += cnt[base + j]; }
    s[tid] = sum;
    __syncthreads();
    for (int off = 1; off < 1024; off <<= 1) {
        int v = (tid >= off) ? s[tid - off] : 0;
        __syncthreads();
        s[tid] += v;
        __syncthreads();
    }
    int excl = tid ? s[tid - 1] : 0;
#pragma unroll
    for (int j = 0; j < 8; j++) {
        rowptr[base + j] = excl + loc[j];
        int c = cnt[base + j];
        Dinv[base + j] = c ? 1.f / (float)c : 0.f;
    }
    if (tid == 1023) rowptr[NN] = s[1023];
}
__global__ void fill_csr(const int* __restrict__ e0, const int* __restrict__ rowptr,
                         int* cursor, int* adj) {
    int i = blockIdx.x * blockDim.x + threadIdx.x;
    if (i >= NZ) return;
    int sg = e0[i];
    int p = atomicAdd(&cursor[sg], 1);
    adj[rowptr[sg] + p] = i;
}

// ----------------- hypergraph pieces -----------------
__global__ void efeat(const int* __restrict__ e0, const float* __restrict__ x, float* ef) {
    int d = blockIdx.x, c = threadIdx.x;
    float a = 0.f;
#pragma unroll 4
    for (int j = 0; j < 32; j++) a += x[e0[d + j * EE] * HH + c];
    ef[d * HH + c] = a;
}

__global__ void rowdot(const float* __restrict__ xw, const float* __restrict__ att,
                       int stride, int heads, float* __restrict__ out) {
    int r = blockIdx.x, h = threadIdx.x >> 5, lane = threadIdx.x & 31;
    const float* row = xw + (size_t)(r * heads + h) * HH;
    float s = 0.f;
#pragma unroll
    for (int m = 0; m < 4; m++) s += row[lane + 32 * m] * att[h * stride + lane + 32 * m];
#pragma unroll
    for (int o = 16; o; o >>= 1) s += __shfl_xor_sync(0xffffffffu, s, o);
    if (!lane) out[r * heads + h] = s;
}

__global__ void alpha_max(const int* __restrict__ e0, const int* __restrict__ e1,
                          const float* __restrict__ xa, const float* __restrict__ ea,
                          int heads) {
    int g = blockIdx.x * blockDim.x + threadIdx.x;
    if (g >= NZ * heads) return;
    int i = g / heads, h = g - i * heads;
    float a = xa[e0[i] * heads + h] + ea[e1[i] * heads + h];
    a = (a > 0.f) ? a : 0.2f * a;
    g_alpha[g] = a;
    atomicMax(&g_segmax[e0[i] * heads + h], fenc(a));
}
__global__ void alpha_exp(const int* __restrict__ e0, int heads) {
    int g = blockIdx.x * blockDim.x + threadIdx.x;
    if (g >= NZ * heads) return;
    int i = g / heads, h = g - i * heads;
    float ex = expf(g_alpha[g] - fdec(g_segmax[e0[i] * heads + h]));
    g_alpha[g] = ex;
    atomicAdd(&g_segsum[e0[i] * heads + h], ex);
}

template <int HT>
__global__ void eout_gather(const int* __restrict__ e0, const float* __restrict__ xw) {
    int d = blockIdx.x, c = threadIdx.x;
    float acc[HT];
#pragma unroll
    for (int h = 0; h < HT; h++) acc[h] = 0.f;
    for (int j = 0; j < 32; j++) {
        int i = d + j * EE, s = e0[i];
#pragma unroll
        for (int h = 0; h < HT; h++) {
            float an = g_alpha[i * HT + h] / (g_segsum[s * HT + h] + 1e-16f);
            acc[h] += an * xw[(size_t)(s * HT + h) * HH + c];
        }
    }
#pragma unroll
    for (int h = 0; h < HT; h++)
        g_eout[(size_t)(d * HT + h) * HH + c] = acc[h] * (1.f / 32.f);
}

template <int HT>
__global__ void node_out(const int* __restrict__ e1, const float* __restrict__ bias,
                         float* __restrict__ out) {
    int s = blockIdx.x, c = threadIdx.x;
    int b = g_rowptr[s], e = g_rowptr[s + 1];
    float ssv[HT];
#pragma unroll
    for (int h = 0; h < HT; h++) ssv[h] = g_segsum[s * HT + h] + 1e-16f;
    float a[HT];
#pragma unroll
    for (int h = 0; h < HT; h++) a[h] = 0.f;
    for (int k = b; k < e; k++) {
        int i = g_adj[k], d = e1[i];
#pragma unroll
        for (int h = 0; h < HT; h++)
            a[h] += (g_alpha[i * HT + h] / ssv[h]) * g_eout[(size_t)(d * HT + h) * HH + c];
    }
    float v = 0.f;
#pragma unroll
    for (int h = 0; h < HT; h++) v += a[h];
    v = v * g_Dinv[s] * (1.f / HT) + bias[c];
    out[s * HH + c] = (v > 0.f) ? v : 0.2f * v;
}

__global__ void head_k(const float* __restrict__ x2, const float* __restrict__ Wo,
                       const float* __restrict__ bo, float* __restrict__ out) {
    int n = blockIdx.x * 4 + (threadIdx.x >> 5), lane = threadIdx.x & 31;
    float s = 0.f;
#pragma unroll
    for (int m = 0; m < 4; m++) s += x2[n * HH + lane + 32 * m] * Wo[lane + 32 * m];
#pragma unroll
    for (int o = 16; o; o >>= 1) s += __shfl_xor_sync(0xffffffffu, s, o);
    if (!lane) {
        float v = s + bo[0];
        out[n] = (v > 0.f) ? v : 0.01f * v;
    }
}

// ----------------- host -----------------
static void* sym(const void* s) { void* p = 0; cudaGetSymbolAddress(&p, s); return p; }

extern "C" void kernel_launch(void* const* d_in, const int* in_sizes, int n_in,
                              void* d_out, int out_size) {
    const float* price = (const float*)d_in[0];
    const int*   e     = (const int*)d_in[1];
    const float* bn1g  = (const float*)d_in[2];
    const float* bn1b  = (const float*)d_in[3];
    const float* Wih   = (const float*)d_in[4];
    const float* Whh   = (const float*)d_in[5];
    const float* bih   = (const float*)d_in[6];
    const float* bhh   = (const float*)d_in[7];
    const float* Wq    = (const float*)d_in[8];
    const float* Wout  = (const float*)d_in[9];
    const float* ae    = (const float*)d_in[10];
    const float* ab    = (const float*)d_in[11];
    const float* bn2g  = (const float*)d_in[12];
    const float* bn2b  = (const float*)d_in[13];
    const float* W1    = (const float*)d_in[14];
    const float* att1  = (const float*)d_in[15];
    const float* bias1 = (const float*)d_in[16];
    const float* W2    = (const float*)d_in[17];
    const float* att2  = (const float*)d_in[18];
    const float* bias2 = (const float*)d_in[19];
    const float* Wo    = (const float*)d_in[20];
    const float* bo    = (const float*)d_in[21];
    const int* e0 = e;
    const int* e1 = e + NZ;

    float* out_nf = (float*)d_out;
    float* out_x  = out_nf + NH;
    float* out_o  = out_x + NH;

    float* p_sum1 = (float*)sym(g_sum1);   float* p_sq1 = (float*)sym(g_sq1);
    float* p_sum2 = (float*)sym(g_sum2);   float* p_sq2 = (float*)sym(g_sq2);
    float* p_sc1 = (float*)sym(g_scale1);  float* p_sh1 = (float*)sym(g_shift1);
    float* p_sc2 = (float*)sym(g_scale2);  float* p_sh2 = (float*)sym(g_shift2);
    float* p_h0 = (float*)sym(g_h0);
    float* p_q = (float*)sym(g_q);         float* p_comb = (float*)sym(g_comb);
    float* p_xbn = (float*)sym(g_xbn);     float* p_ef = (float*)sym(g_ef);
    float* p_xw = (float*)sym(g_xw);       float* p_ew = (float*)sym(g_ew);
    float* p_xa = (float*)sym(g_xa);       float* p_ea = (float*)sym(g_ea);
    float* p_smax = (float*)sym(g_segmax); float* p_ssum = (float*)sym(g_segsum);
    float* p_x1 = (float*)sym(g_x1);
    int* p_cnt = (int*)sym(g_cnt);         int* p_cur = (int*)sym(g_cursor);
    int* p_rp = (int*)sym(g_rowptr);       int* p_adj = (int*)sym(g_adj);
    float* p_Dinv = (float*)sym(g_Dinv);

    // launch 1-3, so launch #4 (ncu capture slot) = gru_persist
    bn_stats<<<16, 1024>>>(price, 512, p_sum1, p_sq1);
    bn_finalize<<<4, 128>>>(p_sum1, p_sq1, bn1g, bn1b, p_sc1, p_sh1, 512);
    prep_all<<<704, 256>>>(Whh, Wih, bih, bhh);

    gru_persist<<<128, 256>>>(price);   // full 32-step GRU, hT -> g_h0, ctx -> g_ctx

    gemm_nt<<<dim3(2, NN / 64), 256>>>(p_h0, Wq, p_q, NN, 128, 128, 0);
    attn_mid<<<NN, 128>>>(ae, ab);
    gemm_nt<<<dim3(2, NN / 64), 256>>>(p_comb, Wout, out_nf, NN, 128, 256, 1);

    bn_stats<<<4, 1024>>>(out_nf, 128, p_sum2, p_sq2);
    bn_finalize<<<1, 128>>>(p_sum2, p_sq2, bn2g, bn2b, p_sc2, p_sh2, 128);
    bn_apply<<<NH / 256, 256>>>(out_nf, p_sc2, p_sh2, p_xbn);

    // CSR by src
    zero_k<<<16, 256>>>((float*)p_cnt, NN);
    count_src<<<NZ / 256, 256>>>(e0, p_cnt);
    scan_csr<<<1, 1024>>>(p_cnt, p_rp, p_Dinv);
    zero_k<<<16, 256>>>((float*)p_cur, NN);
    fill_csr<<<NZ / 256, 256>>>(e0, p_rp, p_cur, p_adj);

    // ---- conv 1 (4 heads) ----
    efeat<<<EE, 128>>>(e0, p_xbn, p_ef);
    gemm_nt<<<dim3(8, NN / 64), 256>>>(p_xbn, W1, p_xw, NN, 512, 128, 0);
    gemm_nt<<<dim3(8, EE / 64), 256>>>(p_ef, W1, p_ew, EE, 512, 128, 0);
    rowdot<<<NN, 128>>>(p_xw, att1, 256, NHEADS, p_xa);
    rowdot<<<EE, 128>>>(p_ew, att1 + 128, 256, NHEADS, p_ea);
    zero_k<<<128, 256>>>((float*)p_smax, NN * NHEADS);
    zero_k<<<128, 256>>>(p_ssum, NN * NHEADS);
    alpha_max<<<NZ * NHEADS / 256, 256>>>(e0, e1, p_xa, p_ea, NHEADS);
    alpha_exp<<<NZ * NHEADS / 256, 256>>>(e0, NHEADS);
    eout_gather<NHEADS><<<EE, 128>>>(e0, p_xw);
    node_out<NHEADS><<<NN, 128>>>(e1, bias1, p_x1);

    // ---- conv 2 (1 head) ----
    efeat<<<EE, 128>>>(e0, p_x1, p_ef);
    gemm_nt<<<dim3(2, NN / 64), 256>>>(p_x1, W2, p_xw, NN, 128, 128, 0);
    gemm_nt<<<dim3(2, EE / 64), 256>>>(p_ef, W2, p_ew, EE, 128, 128, 0);
    rowdot<<<NN, 32>>>(p_xw, att2, 256, 1, p_xa);
    rowdot<<<EE, 32>>>(p_ew, att2 + 128, 256, 1, p_ea);
    zero_k<<<32, 256>>>((float*)p_smax, NN);
    zero_k<<<32, 256>>>(p_ssum, NN);
    alpha_max<<<NZ / 256, 256>>>(e0, e1, p_xa, p_ea, 1);
    alpha_exp<<<NZ / 256, 256>>>(e0, 1);
    eout_gather<1><<<EE, 128>>>(e0, p_xw);
    node_out<1><<<NN, 128>>>(e1, bias2, out_x);

    head_k<<<NN / 4, 128>>>(out_x, Wo, bo, out_o);
}

// round 12
// speedup vs baseline: 2.7492x; 1.0818x over previous
#include <cuda_runtime.h>
#include <math.h>

#define NN 8192
#define TT 32
#define FF 16
#define HH 128
#define NHEADS 4
#define EE 2048
#define NZ 65536
#define NH (NN*HH)

// ----------------- static device scratch (no allocs) -----------------
__device__ float g_scale1[512], g_shift1[512], g_sum1[512], g_sq1[512];
__device__ float g_scale2[HH], g_shift2[HH], g_sum2[HH], g_sq2[HH];
__device__ float g_WfragH[64 * 16 * 32 * 2];       // tf32 B-frags, h-part (256KB)
__device__ float g_WfragX[32 * 64 * 2 * 32 * 2];   // tf32 B-frags, x-part per t (1MB)
__device__ float g_bias[32 * 512];                 // combined per-t bias
__device__ float g_h0[NH];
__device__ float g_ctx[NN * TT * HH];
__device__ float g_q[NH];
__device__ float g_comb[NN * 2 * HH];
__device__ float g_xbn[NH];
__device__ float g_ef[EE * HH];
__device__ float g_xw[NN * 512];
__device__ float g_ew[EE * 512];
__device__ float g_xa[NN * NHEADS];
__device__ float g_ea[EE * NHEADS];
__device__ float g_alpha[NZ * NHEADS];
__device__ unsigned g_segmax[NN * NHEADS];
__device__ float g_segsum[NN * NHEADS];
__device__ float g_Dinv[NN];
__device__ float g_eout[EE * NHEADS * HH];
__device__ float g_x1[NH];
__device__ int g_cnt[NN], g_cursor[NN], g_rowptr[NN + 1], g_adj[NZ];

// ----------------- helpers -----------------
__device__ __forceinline__ unsigned fenc(float a) {
    unsigned u = __float_as_uint(a);
    return (u & 0x80000000u) ? ~u : (u | 0x80000000u);
}
__device__ __forceinline__ float fdec(unsigned u) {
    return (u & 0x80000000u) ? __uint_as_float(u & 0x7FFFFFFFu) : __uint_as_float(~u);
}
__device__ __forceinline__ float tf32r(float x) {
    unsigned u; asm("cvt.rna.tf32.f32 %0, %1;" : "=r"(u) : "f"(x));
    return __uint_as_float(u);
}
__device__ __forceinline__ float sigacc(float x) {
    return __fdividef(1.f, 1.f + __expf(-x));
}
__device__ __forceinline__ float tanhacc(float x) {
    return 1.f - __fdividef(2.f, __expf(2.f * x) + 1.f);
}
__device__ __forceinline__ void mma8(float* c, const unsigned* a, unsigned b0, unsigned b1) {
    asm volatile(
        "mma.sync.aligned.m16n8k8.row.col.f32.tf32.tf32.f32 "
        "{%0,%1,%2,%3}, {%4,%5,%6,%7}, {%8,%9}, {%0,%1,%2,%3};\n"
        : "+f"(c[0]), "+f"(c[1]), "+f"(c[2]), "+f"(c[3])
        : "r"(a[0]), "r"(a[1]), "r"(a[2]), "r"(a[3]), "r"(b0), "r"(b1));
}

__global__ void zero_k(float* p, int n) {
    for (int i = blockIdx.x * blockDim.x + threadIdx.x; i < n; i += gridDim.x * blockDim.x)
        p[i] = 0.f;
}

// ----------------- batchnorm -----------------
__global__ void bn_stats(const float* __restrict__ x, int ncols, float* sum, float* sq) {
    __shared__ float ssum[32 * 33], ssq[32 * 33];
    int c = threadIdx.x & 31, rg = threadIdx.x >> 5;
    int col = blockIdx.x * 32 + c;
    float s = 0.f, q = 0.f;
    for (int r = rg; r < NN; r += 32) {
        float v = x[(size_t)r * ncols + col];
        s += v; q += v * v;
    }
    ssum[rg * 33 + c] = s; ssq[rg * 33 + c] = q;
    __syncthreads();
    if (threadIdx.x < 32) {
        float S = 0.f, Q = 0.f;
        for (int g = 0; g < 32; g++) { S += ssum[g * 33 + threadIdx.x]; Q += ssq[g * 33 + threadIdx.x]; }
        sum[blockIdx.x * 32 + threadIdx.x] = S;
        sq[blockIdx.x * 32 + threadIdx.x] = Q;
    }
}
__global__ void bn_finalize(const float* sum, const float* sq, const float* g,
                            const float* b, float* scale, float* shift, int ncols) {
    int c = blockIdx.x * blockDim.x + threadIdx.x;
    if (c >= ncols) return;
    float m = sum[c] * (1.f / NN);
    float v = sq[c] * (1.f / NN) - m * m;
    float sc = rsqrtf(v + 1e-5f) * g[c];
    scale[c] = sc; shift[c] = b[c] - m * sc;
}
// bn_apply + zero cnt (fused to drop a launch)
__global__ void bn_apply(const float* __restrict__ x, const float* scale,
                         const float* shift, float* y, int* cnt) {
    int i = blockIdx.x * blockDim.x + threadIdx.x;
    if (i >= NH) return;
    int c = i & (HH - 1);
    y[i] = x[i] * scale[c] + shift[c];
    if (i < NN) cnt[i] = 0;
}

// ----------------- GRU prep: fragment-ready tf32 weights + biases -----------------
__global__ void prep_all(const float* __restrict__ Whh, const float* __restrict__ Wih,
                         const float* __restrict__ bih, const float* __restrict__ bhh) {
    int b = blockIdx.x, tid = threadIdx.x;
    if (b < 128) {                       // WfragH: [ntg 64][ks 16][lane 32][2]
        int idx = b * 256 + tid;
        int lane = idx & 31, ks = (idx >> 5) & 15, ntg = idx >> 9;
        int k = ks * 8 + (lane & 3), c = ntg * 8 + (lane >> 2);
        int j = c >> 2, p = c & 3;
        float b0 = 0.f, b1 = 0.f;
        if (p != 2) {
            int g = (p == 3) ? (256 + j) : (p * 128 + j);
            b0 = Whh[g * 128 + k]; b1 = Whh[g * 128 + k + 4];
        }
        g_WfragH[idx * 2] = tf32r(b0); g_WfragH[idx * 2 + 1] = tf32r(b1);
    } else if (b < 640) {                // WfragX: [t 32][ntg 64][ks2 2][lane 32][2]
        int idx = (b - 128) * 256 + tid;
        int lane = idx & 31, ks2 = (idx >> 5) & 1, ntg = (idx >> 6) & 63, t = idx >> 12;
        int f = ks2 * 8 + (lane & 3), c = ntg * 8 + (lane >> 2);
        int j = c >> 2, p = c & 3;
        float b0 = 0.f, b1 = 0.f;
        if (p != 3) {
            int g = p * 128 + j;
            b0 = Wih[g * 16 + f] * g_scale1[t * 16 + f];
            b1 = Wih[g * 16 + f + 4] * g_scale1[t * 16 + f + 4];
        }
        g_WfragX[idx * 2] = tf32r(b0); g_WfragX[idx * 2 + 1] = tf32r(b1);
    } else {                             // bias: [t 32][c 512]
        int idx = (b - 640) * 256 + tid;
        int c = idx & 511, t = idx >> 9;
        int j = c >> 2, p = c & 3;
        float v;
        if (p == 3) v = bhh[256 + j];
        else {
            int g = p * 128 + j;
            float sd = 0.f;
            for (int f = 0; f < 16; f++) sd += g_shift1[t * 16 + f] * Wih[g * 16 + f];
            v = bih[g] + sd + ((p < 2) ? bhh[g] : 0.f);
        }
        g_bias[t * 512 + c] = v;
    }
}

// ----------------- persistent tf32-mma GRU (v2: 512 threads, 16 warps) -----------------
// grid 128 x 512. Block owns 64 nodes; h persists in smem across 32 steps.
// Warp w computes cols [w*32, w*32+32): warp tile m64 x n32, 18 k-steps of k8.
#define GPAD 132
__global__ void __launch_bounds__(512)
gru_persist(const float* __restrict__ price) {
    __shared__ float sh[64 * GPAD];
    __shared__ float sx[64 * 20];
    __shared__ float sbias[512];
    int tid = threadIdx.x, lane = tid & 31, warp = tid >> 5;
    int gid = lane >> 2, q = lane & 3;
    int node0 = blockIdx.x * 64;

    for (int i = tid; i < 64 * GPAD; i += 512) sh[i] = 0.f;
    __syncthreads();

    const float2* __restrict__ WH = (const float2*)g_WfragH;

    for (int t = 0; t < TT; t++) {
        for (int i = tid; i < 1024; i += 512) {
            int nd = i >> 4, f = i & 15;
            sx[nd * 20 + f] = tf32r(price[(size_t)(node0 + nd) * 512 + t * 16 + f]);
        }
        if (tid < 512) sbias[tid] = g_bias[t * 512 + tid];
        __syncthreads();   // A

        const float2* __restrict__ WXt = (const float2*)g_WfragX + (size_t)t * 4096;

        float acc[4][4][4];
#pragma unroll
        for (int mt = 0; mt < 4; mt++)
#pragma unroll
            for (int nt = 0; nt < 4; nt++) {
                int cb = warp * 32 + nt * 8 + 2 * q;
                float2 bv = *(const float2*)&sbias[cb];
                acc[mt][nt][0] = bv.x; acc[mt][nt][1] = bv.y;
                acc[mt][nt][2] = bv.x; acc[mt][nt][3] = bv.y;
            }

        float2 bcur[4], bnxt[4];
#pragma unroll
        for (int nt = 0; nt < 4; nt++)
            bcur[nt] = WH[(((warp * 4 + nt) * 16) + 0) * 32 + lane];

        for (int ks = 0; ks < 18; ks++) {
            if (ks < 17) {
                int kn = ks + 1;
                if (kn < 16) {
#pragma unroll
                    for (int nt = 0; nt < 4; nt++)
                        bnxt[nt] = WH[(((warp * 4 + nt) * 16) + kn) * 32 + lane];
                } else {
                    int ks2 = kn - 16;
#pragma unroll
                    for (int nt = 0; nt < 4; nt++)
                        bnxt[nt] = WXt[(((warp * 4 + nt) * 2) + ks2) * 32 + lane];
                }
            }
            unsigned a[4][4];
            if (ks < 16) {
                int base = ks * 8 + q;
#pragma unroll
                for (int mt = 0; mt < 4; mt++) {
                    int r0 = mt * 16 + gid;
                    a[mt][0] = __float_as_uint(sh[r0 * GPAD + base]);
                    a[mt][1] = __float_as_uint(sh[(r0 + 8) * GPAD + base]);
                    a[mt][2] = __float_as_uint(sh[r0 * GPAD + base + 4]);
                    a[mt][3] = __float_as_uint(sh[(r0 + 8) * GPAD + base + 4]);
                }
            } else {
                int base = (ks - 16) * 8 + q;
#pragma unroll
                for (int mt = 0; mt < 4; mt++) {
                    int r0 = mt * 16 + gid;
                    a[mt][0] = __float_as_uint(sx[r0 * 20 + base]);
                    a[mt][1] = __float_as_uint(sx[(r0 + 8) * 20 + base]);
                    a[mt][2] = __float_as_uint(sx[r0 * 20 + base + 4]);
                    a[mt][3] = __float_as_uint(sx[(r0 + 8) * 20 + base + 4]);
                }
            }
#pragma unroll
            for (int nt = 0; nt < 4; nt++) {
                unsigned b0 = __float_as_uint(bcur[nt].x), b1 = __float_as_uint(bcur[nt].y);
#pragma unroll
                for (int mt = 0; mt < 4; mt++) mma8(acc[mt][nt], a[mt], b0, b1);
            }
#pragma unroll
            for (int nt = 0; nt < 4; nt++) bcur[nt] = bnxt[nt];
        }

        __syncthreads();   // B

        // epilogue: q-parity lane pairing (even: r,z | odd: nx,nh of same j)
#pragma unroll
        for (int mt = 0; mt < 4; mt++)
#pragma unroll
            for (int nt = 0; nt < 4; nt++) {
                float c0 = acc[mt][nt][0], c1 = acc[mt][nt][1];
                float c2 = acc[mt][nt][2], c3 = acc[mt][nt][3];
                float v0 = __shfl_xor_sync(0xffffffffu, c0, 1);
                float v1 = __shfl_xor_sync(0xffffffffu, c1, 1);
                float v2 = __shfl_xor_sync(0xffffffffu, c2, 1);
                float v3 = __shfl_xor_sync(0xffffffffu, c3, 1);
                int cb = warp * 32 + nt * 8 + 2 * q;
                int j = cb >> 2;
                float ra, za, nx, nh; int row;
                if ((q & 1) == 0) { row = mt * 16 + gid;     ra = c0; za = c1; nx = v0; nh = v1; }
                else              { row = mt * 16 + gid + 8; ra = v2; za = v3; nx = c2; nh = c3; }
                float r = sigacc(ra), z = sigacc(za);
                float n = tanhacc(nx + r * nh);
                float hold = sh[row * GPAD + j];
                sh[row * GPAD + j] = tf32r((1.f - z) * n + z * hold);
            }
        __syncthreads();   // C

        size_t cbase = (size_t)node0 * 4096 + (size_t)t * 128;
        for (int i = tid; i < 2048; i += 512) {
            int nd = i >> 5, jq = i & 31;
            float4 v = *(const float4*)&sh[nd * GPAD + jq * 4];
            *(float4*)&g_ctx[cbase + (size_t)nd * 4096 + jq * 4] = v;
            if (t == 31) *(float4*)&g_h0[(size_t)(node0 + nd) * 128 + jq * 4] = v;
        }
    }
}

// ----------------- generic NT sgemm: C = act(A(M,K) @ B(Nc,K)^T) -----------------
__global__ void gemm_nt(const float* __restrict__ A, const float* __restrict__ B,
                        float* __restrict__ C, int M, int Nc, int K, int act) {
    __shared__ float As[16 * 68], Bs[16 * 68];
    int tid = threadIdx.x, n0 = blockIdx.x * 64, m0 = blockIdx.y * 64;
    int lrow = tid >> 2, kq = tid & 3, tx = tid & 15, ty = tid >> 4;
    float c[4][4];
#pragma unroll
    for (int i = 0; i < 4; i++)
#pragma unroll
        for (int jv = 0; jv < 4; jv++) c[i][jv] = 0.f;

    for (int k0 = 0; k0 < K; k0 += 16) {
        float4 av = *(const float4*)&A[(size_t)(m0 + lrow) * K + k0 + kq * 4];
        float4 bv = *(const float4*)&B[(size_t)(n0 + lrow) * K + k0 + kq * 4];
        __syncthreads();
        As[(kq*4+0)*68+lrow] = av.x; As[(kq*4+1)*68+lrow] = av.y;
        As[(kq*4+2)*68+lrow] = av.z; As[(kq*4+3)*68+lrow] = av.w;
        Bs[(kq*4+0)*68+lrow] = bv.x; Bs[(kq*4+1)*68+lrow] = bv.y;
        Bs[(kq*4+2)*68+lrow] = bv.z; Bs[(kq*4+3)*68+lrow] = bv.w;
        __syncthreads();
#pragma unroll
        for (int kk = 0; kk < 16; kk++) {
            float4 a = *(const float4*)&As[kk * 68 + ty * 4];
            float4 b = *(const float4*)&Bs[kk * 68 + tx * 4];
            float ar[4] = {a.x, a.y, a.z, a.w}, br[4] = {b.x, b.y, b.z, b.w};
#pragma unroll
            for (int i = 0; i < 4; i++)
#pragma unroll
                for (int jv = 0; jv < 4; jv++) c[i][jv] += ar[i] * br[jv];
        }
    }
#pragma unroll
    for (int i = 0; i < 4; i++)
#pragma unroll
        for (int jv = 0; jv < 4; jv++) {
            float v = c[i][jv];
            if (act == 1) v = tanhf(v);
            C[(size_t)(m0 + ty * 4 + i) * Nc + n0 + tx * 4 + jv] = v;
        }
}

// ----------------- temporal attention middle -----------------
__global__ void attn_mid(const float* __restrict__ ae, const float* __restrict__ ab) {
    __shared__ float sctx[32 * 129], sq[128], sw[32], sbt[32];
    int n = blockIdx.x, tid = threadIdx.x;
    sq[tid] = g_q[n * HH + tid];
    for (int idx = tid; idx < TT * HH; idx += 128) {
        int t = idx >> 7, k = idx & 127;
        sctx[t * 129 + k] = g_ctx[(size_t)n * (TT * HH) + idx];
    }
    __syncthreads();
    if (tid < 32) {
        float s = 0.f;
        for (int k = 0; k < 128; k++) s += sq[k] * sctx[tid * 129 + k];
        float m = s;
#pragma unroll
        for (int o = 16; o; o >>= 1) m = fmaxf(m, __shfl_xor_sync(0xffffffffu, m, o));
        float e = expf(s - m), su = e;
#pragma unroll
        for (int o = 16; o; o >>= 1) su += __shfl_xor_sync(0xffffffffu, su, o);
        sw[tid] = e / su;
        sbt[tid] = expf(-ab[n] * (float)(31 - tid));
    }
    __syncthreads();
    float aen = ae[n], acc = 0.f;
#pragma unroll 4
    for (int t = 0; t < TT; t++) {
        float mx = sw[t] * sctx[t * 129 + tid];
        acc += mx + fmaxf(aen * mx * sbt[t], 0.f);
    }
    g_comb[n * 256 + tid] = acc;
    g_comb[n * 256 + 128 + tid] = sq[tid];
}

// ----------------- CSR build (by src) -----------------
__global__ void count_src(const int* __restrict__ e0, int* cnt) {
    int i = blockIdx.x * blockDim.x + threadIdx.x;
    if (i < NZ) atomicAdd(&cnt[e0[i]], 1);
}
// scan + cursor zero (fused)
__global__ void scan_csr(const int* __restrict__ cnt, int* rowptr, float* Dinv, int* cursor) {
    __shared__ int s[1024];
    int tid = threadIdx.x, base = tid * 8, loc[8], sum = 0;
#pragma unroll
    for (int j = 0; j < 8; j++) { loc[j] = sum; sum += cnt[base + j]; }
    s[tid] = sum;
    __syncthreads();
    for (int off = 1; off < 1024; off <<= 1) {
        int v = (tid >= off) ? s[tid - off] : 0;
        __syncthreads();
        s[tid] += v;
        __syncthreads();
    }
    int excl = tid ? s[tid - 1] : 0;
#pragma unroll
    for (int j = 0; j < 8; j++) {
        rowptr[base + j] = excl + loc[j];
        int c = cnt[base + j];
        Dinv[base + j] = c ? 1.f / (float)c : 0.f;
        cursor[base + j] = 0;
    }
    if (tid == 1023) rowptr[NN] = s[1023];
}
// fill + zero segmax/segsum for conv1 (fused)
__global__ void fill_csr(const int* __restrict__ e0, const int* __restrict__ rowptr,
                         int* cursor, int* adj, unsigned* segmax, float* segsum) {
    int i = blockIdx.x * blockDim.x + threadIdx.x;
    if (i >= NZ) return;
    if (i < NN * NHEADS) { segmax[i] = 0u; segsum[i] = 0.f; }
    int sg = e0[i];
    int p = atomicAdd(&cursor[sg], 1);
    adj[rowptr[sg] + p] = i;
}

// ----------------- hypergraph pieces -----------------
// efeat; optionally zeroes first NN entries of segmax/segsum for the next conv
__global__ void efeat(const int* __restrict__ e0, const float* __restrict__ x, float* ef,
                      unsigned* segmax, float* segsum, int zeroseg) {
    int d = blockIdx.x, c = threadIdx.x;
    if (zeroseg) {
        int gid = d * 128 + c;
        if (gid < NN) { segmax[gid] = 0u; segsum[gid] = 0.f; }
    }
    float a = 0.f;
#pragma unroll 4
    for (int j = 0; j < 32; j++) a += x[e0[d + j * EE] * HH + c];
    ef[d * HH + c] = a;
}

__global__ void rowdot(const float* __restrict__ xw, const float* __restrict__ att,
                       int stride, int heads, float* __restrict__ out) {
    int r = blockIdx.x, h = threadIdx.x >> 5, lane = threadIdx.x & 31;
    const float* row = xw + (size_t)(r * heads + h) * HH;
    float s = 0.f;
#pragma unroll
    for (int m = 0; m < 4; m++) s += row[lane + 32 * m] * att[h * stride + lane + 32 * m];
#pragma unroll
    for (int o = 16; o; o >>= 1) s += __shfl_xor_sync(0xffffffffu, s, o);
    if (!lane) out[r * heads + h] = s;
}

__global__ void alpha_max(const int* __restrict__ e0, const int* __restrict__ e1,
                          const float* __restrict__ xa, const float* __restrict__ ea,
                          int heads) {
    int g = blockIdx.x * blockDim.x + threadIdx.x;
    if (g >= NZ * heads) return;
    int i = g / heads, h = g - i * heads;
    float a = xa[e0[i] * heads + h] + ea[e1[i] * heads + h];
    a = (a > 0.f) ? a : 0.2f * a;
    g_alpha[g] = a;
    atomicMax(&g_segmax[e0[i] * heads + h], fenc(a));
}
__global__ void alpha_exp(const int* __restrict__ e0, int heads) {
    int g = blockIdx.x * blockDim.x + threadIdx.x;
    if (g >= NZ * heads) return;
    int i = g / heads, h = g - i * heads;
    float ex = expf(g_alpha[g] - fdec(g_segmax[e0[i] * heads + h]));
    g_alpha[g] = ex;
    atomicAdd(&g_segsum[e0[i] * heads + h], ex);
}

template <int HT>
__global__ void eout_gather(const int* __restrict__ e0, const float* __restrict__ xw) {
    int d = blockIdx.x, c = threadIdx.x;
    float acc[HT];
#pragma unroll
    for (int h = 0; h < HT; h++) acc[h] = 0.f;
    for (int j = 0; j < 32; j++) {
        int i = d + j * EE, s = e0[i];
#pragma unroll
        for (int h = 0; h < HT; h++) {
            float an = g_alpha[i * HT + h] / (g_segsum[s * HT + h] + 1e-16f);
            acc[h] += an * xw[(size_t)(s * HT + h) * HH + c];
        }
    }
#pragma unroll
    for (int h = 0; h < HT; h++)
        g_eout[(size_t)(d * HT + h) * HH + c] = acc[h] * (1.f / 32.f);
}

template <int HT>
__global__ void node_out(const int* __restrict__ e1, const float* __restrict__ bias,
                         float* __restrict__ out) {
    int s = blockIdx.x, c = threadIdx.x;
    int b = g_rowptr[s], e = g_rowptr[s + 1];
    float ssv[HT];
#pragma unroll
    for (int h = 0; h < HT; h++) ssv[h] = g_segsum[s * HT + h] + 1e-16f;
    float a[HT];
#pragma unroll
    for (int h = 0; h < HT; h++) a[h] = 0.f;
    for (int k = b; k < e; k++) {
        int i = g_adj[k], d = e1[i];
#pragma unroll
        for (int h = 0; h < HT; h++)
            a[h] += (g_alpha[i * HT + h] / ssv[h]) * g_eout[(size_t)(d * HT + h) * HH + c];
    }
    float v = 0.f;
#pragma unroll
    for (int h = 0; h < HT; h++) v += a[h];
    v = v * g_Dinv[s] * (1.f / HT) + bias[c];
    out[s * HH + c] = (v > 0.f) ? v : 0.2f * v;
}

__global__ void head_k(const float* __restrict__ x2, const float* __restrict__ Wo,
                       const float* __restrict__ bo, float* __restrict__ out) {
    int n = blockIdx.x * 4 + (threadIdx.x >> 5), lane = threadIdx.x & 31;
    float s = 0.f;
#pragma unroll
    for (int m = 0; m < 4; m++) s += x2[n * HH + lane + 32 * m] * Wo[lane + 32 * m];
#pragma unroll
    for (int o = 16; o; o >>= 1) s += __shfl_xor_sync(0xffffffffu, s, o);
    if (!lane) {
        float v = s + bo[0];
        out[n] = (v > 0.f) ? v : 0.01f * v;
    }
}

// ----------------- host -----------------
static void* sym(const void* s) { void* p = 0; cudaGetSymbolAddress(&p, s); return p; }

extern "C" void kernel_launch(void* const* d_in, const int* in_sizes, int n_in,
                              void* d_out, int out_size) {
    const float* price = (const float*)d_in[0];
    const int*   e     = (const int*)d_in[1];
    const float* bn1g  = (const float*)d_in[2];
    const float* bn1b  = (const float*)d_in[3];
    const float* Wih   = (const float*)d_in[4];
    const float* Whh   = (const float*)d_in[5];
    const float* bih   = (const float*)d_in[6];
    const float* bhh   = (const float*)d_in[7];
    const float* Wq    = (const float*)d_in[8];
    const float* Wout  = (const float*)d_in[9];
    const float* ae    = (const float*)d_in[10];
    const float* ab    = (const float*)d_in[11];
    const float* bn2g  = (const float*)d_in[12];
    const float* bn2b  = (const float*)d_in[13];
    const float* W1    = (const float*)d_in[14];
    const float* att1  = (const float*)d_in[15];
    const float* bias1 = (const float*)d_in[16];
    const float* W2    = (const float*)d_in[17];
    const float* att2  = (const float*)d_in[18];
    const float* bias2 = (const float*)d_in[19];
    const float* Wo    = (const float*)d_in[20];
    const float* bo    = (const float*)d_in[21];
    const int* e0 = e;
    const int* e1 = e + NZ;

    float* out_nf = (float*)d_out;
    float* out_x  = out_nf + NH;
    float* out_o  = out_x + NH;

    float* p_sum1 = (float*)sym(g_sum1);   float* p_sq1 = (float*)sym(g_sq1);
    float* p_sum2 = (float*)sym(g_sum2);   float* p_sq2 = (float*)sym(g_sq2);
    float* p_sc1 = (float*)sym(g_scale1);  float* p_sh1 = (float*)sym(g_shift1);
    float* p_sc2 = (float*)sym(g_scale2);  float* p_sh2 = (float*)sym(g_shift2);
    float* p_h0 = (float*)sym(g_h0);
    float* p_q = (float*)sym(g_q);         float* p_comb = (float*)sym(g_comb);
    float* p_xbn = (float*)sym(g_xbn);     float* p_ef = (float*)sym(g_ef);
    float* p_xw = (float*)sym(g_xw);       float* p_ew = (float*)sym(g_ew);
    float* p_xa = (float*)sym(g_xa);       float* p_ea = (float*)sym(g_ea);
    unsigned* p_smax = (unsigned*)sym(g_segmax);
    float* p_ssum = (float*)sym(g_segsum);
    float* p_x1 = (float*)sym(g_x1);
    int* p_cnt = (int*)sym(g_cnt);         int* p_cur = (int*)sym(g_cursor);
    int* p_rp = (int*)sym(g_rowptr);       int* p_adj = (int*)sym(g_adj);
    float* p_Dinv = (float*)sym(g_Dinv);

    // launches 1-3, so launch #4 (ncu capture slot) = gru_persist
    bn_stats<<<16, 1024>>>(price, 512, p_sum1, p_sq1);
    bn_finalize<<<4, 128>>>(p_sum1, p_sq1, bn1g, bn1b, p_sc1, p_sh1, 512);
    prep_all<<<704, 256>>>(Whh, Wih, bih, bhh);

    gru_persist<<<128, 512>>>(price);   // full 32-step GRU, hT -> g_h0, ctx -> g_ctx

    gemm_nt<<<dim3(2, NN / 64), 256>>>(p_h0, Wq, p_q, NN, 128, 128, 0);
    attn_mid<<<NN, 128>>>(ae, ab);
    gemm_nt<<<dim3(2, NN / 64), 256>>>(p_comb, Wout, out_nf, NN, 128, 256, 1);

    bn_stats<<<4, 1024>>>(out_nf, 128, p_sum2, p_sq2);
    bn_finalize<<<1, 128>>>(p_sum2, p_sq2, bn2g, bn2b, p_sc2, p_sh2, 128);
    bn_apply<<<NH / 256, 256>>>(out_nf, p_sc2, p_sh2, p_xbn, p_cnt);

    // CSR by src (cursor zero fused in scan, seg zero fused in fill)
    count_src<<<NZ / 256, 256>>>(e0, p_cnt);
    scan_csr<<<1, 1024>>>(p_cnt, p_rp, p_Dinv, p_cur);
    fill_csr<<<NZ / 256, 256>>>(e0, p_rp, p_cur, p_adj, p_smax, p_ssum);

    // ---- conv 1 (4 heads) ----
    efeat<<<EE, 128>>>(e0, p_xbn, p_ef, p_smax, p_ssum, 0);
    gemm_nt<<<dim3(8, NN / 64), 256>>>(p_xbn, W1, p_xw, NN, 512, 128, 0);
    gemm_nt<<<dim3(8, EE / 64), 256>>>(p_ef, W1, p_ew, EE, 512, 128, 0);
    rowdot<<<NN, 128>>>(p_xw, att1, 256, NHEADS, p_xa);
    rowdot<<<EE, 128>>>(p_ew, att1 + 128, 256, NHEADS, p_ea);
    alpha_max<<<NZ * NHEADS / 256, 256>>>(e0, e1, p_xa, p_ea, NHEADS);
    alpha_exp<<<NZ * NHEADS / 256, 256>>>(e0, NHEADS);
    eout_gather<NHEADS><<<EE, 128>>>(e0, p_xw);
    node_out<NHEADS><<<NN, 128>>>(e1, bias1, p_x1);

    // ---- conv 2 (1 head) ----  (efeat also zeroes segmax/segsum[0:NN])
    efeat<<<EE, 128>>>(e0, p_x1, p_ef, p_smax, p_ssum, 1);
    gemm_nt<<<dim3(2, NN / 64), 256>>>(p_x1, W2, p_xw, NN, 128, 128, 0);
    gemm_nt<<<dim3(2, EE / 64), 256>>>(p_ef, W2, p_ew, EE, 128, 128, 0);
    rowdot<<<NN, 32>>>(p_xw, att2, 256, 1, p_xa);
    rowdot<<<EE, 32>>>(p_ew, att2 + 128, 256, 1, p_ea);
    alpha_max<<<NZ / 256, 256>>>(e0, e1, p_xa, p_ea, 1);
    alpha_exp<<<NZ / 256, 256>>>(e0, 1);
    eout_gather<1><<<EE, 128>>>(e0, p_xw);
    node_out<1><<<NN, 128>>>(e1, bias2, out_x);

    head_k<<<NN / 4, 128>>>(out_x, Wo, bo, out_o);
}